// round 5
// baseline (speedup 1.0000x reference)
#include <cuda_runtime.h>
#include <cuda_bf16.h>
#include <math.h>
#include <stdint.h>

#define BATCH 8192
#define HID   1024
#define FH    96
#define O_DIM 8
#define E_DIM 36
#define NM    768
#define NV    3456

// ---------------------------------------------------------------------------
// Device scratch (allocation-free per harness rules)
// ---------------------------------------------------------------------------
__device__ __nv_bfloat16 g_zhi[(size_t)BATCH * HID];
__device__ __nv_bfloat16 g_zlo[(size_t)BATCH * HID];
__device__ __nv_bfloat16 g_ihi[(size_t)BATCH * HID];
__device__ __nv_bfloat16 g_ilo[(size_t)BATCH * HID];
__device__ __nv_bfloat16 g_hhi[(size_t)BATCH * HID];
__device__ __nv_bfloat16 g_hlo[(size_t)BATCH * HID];
__device__ __nv_bfloat16 g_w1hi[(size_t)HID * HID];
__device__ __nv_bfloat16 g_w1lo[(size_t)HID * HID];
__device__ __nv_bfloat16 g_w2hi[(size_t)HID * HID];
__device__ __nv_bfloat16 g_w2lo[(size_t)HID * HID];
__device__ __nv_bfloat16 g_wmhi[(size_t)NM * HID];
__device__ __nv_bfloat16 g_wmlo[(size_t)NM * HID];
__device__ __nv_bfloat16 g_wvhi[(size_t)NV * HID];
__device__ __nv_bfloat16 g_wvlo[(size_t)NV * HID];
__device__ float         g_lv[(size_t)BATCH * NV];

// ---------------------------------------------------------------------------
// helpers
// ---------------------------------------------------------------------------
__device__ __forceinline__ uint32_t smem_u32(const void* p) {
    uint32_t a;
    asm("{ .reg .u64 t; cvta.to.shared.u64 t, %1; cvt.u32.u64 %0, t; }" : "=r"(a) : "l"(p));
    return a;
}

__device__ __forceinline__ void cp16(uint32_t dst, const void* src) {
    asm volatile("cp.async.cg.shared.global [%0], [%1], 16;" :: "r"(dst), "l"(src));
}
#define CP_COMMIT() asm volatile("cp.async.commit_group;" ::: "memory")
#define CP_WAIT0()  asm volatile("cp.async.wait_group 0;"  ::: "memory")

__device__ __forceinline__ void mma16816(float* d, const uint32_t* a, const uint32_t* b)
{
    asm volatile(
        "mma.sync.aligned.m16n8k16.row.col.f32.bf16.bf16.f32 "
        "{%0,%1,%2,%3},{%4,%5,%6,%7},{%8,%9},{%0,%1,%2,%3};\n"
        : "+f"(d[0]), "+f"(d[1]), "+f"(d[2]), "+f"(d[3])
        : "r"(a[0]), "r"(a[1]), "r"(a[2]), "r"(a[3]), "r"(b[0]), "r"(b[1]));
}

__device__ __forceinline__ uint32_t bfpack2(float a, float b) {
    __nv_bfloat162 t = __halves2bfloat162(__float2bfloat16(a), __float2bfloat16(b));
    return *reinterpret_cast<uint32_t*>(&t);
}

// ---------------------------------------------------------------------------
// split_act: fp32 [n] -> hi bf16 [n], lo bf16 [n]
// ---------------------------------------------------------------------------
__global__ __launch_bounds__(256)
void split_act(const float* __restrict__ x,
               __nv_bfloat16* __restrict__ hi, __nv_bfloat16* __restrict__ lo)
{
    size_t idx = ((size_t)blockIdx.x * blockDim.x + threadIdx.x) * 4;
    float4 v = *(const float4*)(x + idx);
    __nv_bfloat16 h0 = __float2bfloat16(v.x), h1 = __float2bfloat16(v.y);
    __nv_bfloat16 h2 = __float2bfloat16(v.z), h3 = __float2bfloat16(v.w);
    uint2 hp, lp;
    { __nv_bfloat162 a = __halves2bfloat162(h0, h1), b = __halves2bfloat162(h2, h3);
      hp.x = *(uint32_t*)&a; hp.y = *(uint32_t*)&b; }
    lp.x = bfpack2(v.x - __bfloat162float(h0), v.y - __bfloat162float(h1));
    lp.y = bfpack2(v.z - __bfloat162float(h2), v.w - __bfloat162float(h3));
    *(uint2*)(hi + idx) = hp;
    *(uint2*)(lo + idx) = lp;
}

// ---------------------------------------------------------------------------
// split_w: W fp32 [K, N] -> Wt hi/lo bf16 [N, K] (transposed + split)
// ---------------------------------------------------------------------------
__global__ __launch_bounds__(256)
void split_w(const float* __restrict__ W,
             __nv_bfloat16* __restrict__ Whi, __nv_bfloat16* __restrict__ Wlo,
             int K, int N)
{
    __shared__ float tile[32][33];
    const int k0 = blockIdx.y * 32, n0 = blockIdx.x * 32;
    const int tx = threadIdx.x & 31, ty = threadIdx.x >> 5;
#pragma unroll
    for (int r = ty; r < 32; r += 8)
        tile[r][tx] = W[(size_t)(k0 + r) * N + n0 + tx];
    __syncthreads();
#pragma unroll
    for (int i = threadIdx.x; i < 32 * 16; i += 256) {
        int nl = i >> 4, kp = i & 15;
        float a = tile[2 * kp][nl], b = tile[2 * kp + 1][nl];
        __nv_bfloat16 ha = __float2bfloat16(a), hb = __float2bfloat16(b);
        size_t base = (size_t)(n0 + nl) * K + k0 + 2 * kp;
        *(uint32_t*)(Whi + base) = bfpack2(a, b);
        *(uint32_t*)(Wlo + base) = bfpack2(a - __bfloat162float(ha), b - __bfloat162float(hb));
    }
}

// ---------------------------------------------------------------------------
// bf16x3 GEMM, pre-split inputs: C[M,N] = act(A @ Bt^T + bias)
// CTA 128x128, BK=32, 4 warps (2M x 2N), warp tile 64x64, 2 CTAs/SM.
// OUTMODE 0: fp32 out Cf. OUTMODE 1: bf16 hi/lo out (Chi/Clo).
// ---------------------------------------------------------------------------
template <bool SILU, int OUTMODE>
__global__ __launch_bounds__(128, 2)
void gemm_mma(int N,
              const __nv_bfloat16* __restrict__ Ahi, const __nv_bfloat16* __restrict__ Alo,
              const __nv_bfloat16* __restrict__ Bthi, const __nv_bfloat16* __restrict__ Btlo,
              const float* __restrict__ bias,
              float* __restrict__ Cf,
              __nv_bfloat16* __restrict__ Chi, __nv_bfloat16* __restrict__ Clo)
{
    constexpr int K = HID;
    constexpr int NITER = K / 32;          // 32 stages
    constexpr int RS = 80;                 // row stride bytes (32 bf16 = 64B + 16B pad)
    constexpr int SA_HI = 0;
    constexpr int SA_LO = 128 * RS;        // 10240
    constexpr int SB_HI = 2 * 128 * RS;    // 20480
    constexpr int SB_LO = 3 * 128 * RS;    // 30720
    constexpr int STAGE = 4 * 128 * RS;    // 40960
    constexpr int BIASOFF = 2 * STAGE;     // 81920

    extern __shared__ __align__(128) char smem[];
    const uint32_t sb = smem_u32(smem);
    float* sBias = (float*)(smem + BIASOFF);

    const int tid  = threadIdx.x;
    const int lane = tid & 31;
    const int wid  = tid >> 5;
    const int g = lane >> 2;               // 0..7
    const int t = lane & 3;                // 0..3
    const int m0 = (wid & 1) * 64;         // 2 warps along M
    const int n0 = (wid >> 1) * 64;        // 2 warps along N

    const int blockM = blockIdx.y * 128;
    const int blockN = blockIdx.x * 128;

    sBias[tid] = bias[blockN + tid];

    const __nv_bfloat16* Ahi_b = Ahi + (size_t)(blockM + tid) * K;
    const __nv_bfloat16* Alo_b = Alo + (size_t)(blockM + tid) * K;
    const __nv_bfloat16* Bhi_b = Bthi + (size_t)(blockN + tid) * K;
    const __nv_bfloat16* Blo_b = Btlo + (size_t)(blockN + tid) * K;

    // Per stage: each thread owns one row of A and one row of B (4x16B chunks each,
    // hi and lo) -> 16 cp.async per thread.
    auto load_stage = [&](int s) {
        const int k0 = s * 32;
        const uint32_t buf = sb + (s & 1) * STAGE;
        const uint32_t rowoff = tid * RS;
#pragma unroll
        for (int ch = 0; ch < 4; ch++) {
            const uint32_t so = rowoff + ch * 16;
            const size_t go = k0 + ch * 8;
            cp16(buf + SA_HI + so, Ahi_b + go);
            cp16(buf + SA_LO + so, Alo_b + go);
            cp16(buf + SB_HI + so, Bhi_b + go);
            cp16(buf + SB_LO + so, Blo_b + go);
        }
    };

    float acc[4][8][4];
#pragma unroll
    for (int mt = 0; mt < 4; mt++)
#pragma unroll
        for (int nt = 0; nt < 8; nt++)
#pragma unroll
            for (int c = 0; c < 4; c++) acc[mt][nt][c] = 0.f;

    load_stage(0);
    CP_COMMIT();

    for (int it = 0; it < NITER; ++it) {
        CP_WAIT0();
        __syncthreads();
        if (it + 1 < NITER) { load_stage(it + 1); CP_COMMIT(); }

        const uint32_t buf = sb + (it & 1) * STAGE;
        const uint32_t aHi = buf + SA_HI, aLo = buf + SA_LO;
        const uint32_t bHi = buf + SB_HI, bLo = buf + SB_LO;

#pragma unroll
        for (int ks = 0; ks < 2; ks++) {
            const uint32_t ko = ks * 32 + t * 4;

            uint32_t fAhi[4][4], fAlo[4][4], fB[8][2];
#pragma unroll
            for (int mt = 0; mt < 4; mt++) {
                const int r = m0 + mt * 16;
                const uint32_t o0 = (r + g) * RS + ko;
                const uint32_t o1 = (r + g + 8) * RS + ko;
                asm volatile("ld.shared.b32 %0, [%1];" : "=r"(fAhi[mt][0]) : "r"(aHi + o0));
                asm volatile("ld.shared.b32 %0, [%1];" : "=r"(fAhi[mt][1]) : "r"(aHi + o1));
                asm volatile("ld.shared.b32 %0, [%1];" : "=r"(fAhi[mt][2]) : "r"(aHi + o0 + 16));
                asm volatile("ld.shared.b32 %0, [%1];" : "=r"(fAhi[mt][3]) : "r"(aHi + o1 + 16));
                asm volatile("ld.shared.b32 %0, [%1];" : "=r"(fAlo[mt][0]) : "r"(aLo + o0));
                asm volatile("ld.shared.b32 %0, [%1];" : "=r"(fAlo[mt][1]) : "r"(aLo + o1));
                asm volatile("ld.shared.b32 %0, [%1];" : "=r"(fAlo[mt][2]) : "r"(aLo + o0 + 16));
                asm volatile("ld.shared.b32 %0, [%1];" : "=r"(fAlo[mt][3]) : "r"(aLo + o1 + 16));
            }
#pragma unroll
            for (int nt = 0; nt < 8; nt++) {
                const uint32_t o = (n0 + nt * 8 + g) * RS + ko;
                asm volatile("ld.shared.b32 %0, [%1];" : "=r"(fB[nt][0]) : "r"(bHi + o));
                asm volatile("ld.shared.b32 %0, [%1];" : "=r"(fB[nt][1]) : "r"(bHi + o + 16));
            }
            // pass 1: hi*hi ; pass 2: loA*hiB
#pragma unroll
            for (int mt = 0; mt < 4; mt++)
#pragma unroll
                for (int nt = 0; nt < 8; nt++) {
                    mma16816(acc[mt][nt], fAhi[mt], fB[nt]);
                    mma16816(acc[mt][nt], fAlo[mt], fB[nt]);
                }
            // reload B lo, pass 3: hiA*loB
#pragma unroll
            for (int nt = 0; nt < 8; nt++) {
                const uint32_t o = (n0 + nt * 8 + g) * RS + ko;
                asm volatile("ld.shared.b32 %0, [%1];" : "=r"(fB[nt][0]) : "r"(bLo + o));
                asm volatile("ld.shared.b32 %0, [%1];" : "=r"(fB[nt][1]) : "r"(bLo + o + 16));
            }
#pragma unroll
            for (int mt = 0; mt < 4; mt++)
#pragma unroll
                for (int nt = 0; nt < 8; nt++)
                    mma16816(acc[mt][nt], fAhi[mt], fB[nt]);
        }
    }

    // epilogue
#pragma unroll
    for (int mt = 0; mt < 4; mt++) {
        const int row0 = blockM + m0 + mt * 16 + g;
#pragma unroll
        for (int nt = 0; nt < 8; nt++) {
            const int coll = n0 + nt * 8 + 2 * t;
            const int col  = blockN + coll;
            const float bv0 = sBias[coll], bv1 = sBias[coll + 1];
            float v00 = acc[mt][nt][0] + bv0, v01 = acc[mt][nt][1] + bv1;
            float v10 = acc[mt][nt][2] + bv0, v11 = acc[mt][nt][3] + bv1;
            if (SILU) {
                v00 = v00 / (1.f + expf(-v00));
                v01 = v01 / (1.f + expf(-v01));
                v10 = v10 / (1.f + expf(-v10));
                v11 = v11 / (1.f + expf(-v11));
            }
            if (OUTMODE == 0) {
                float2 a = {v00, v01}, b = {v10, v11};
                *(float2*)(Cf + (size_t)row0 * N + col)       = a;
                *(float2*)(Cf + (size_t)(row0 + 8) * N + col) = b;
            } else {
                __nv_bfloat16 h00 = __float2bfloat16(v00), h01 = __float2bfloat16(v01);
                __nv_bfloat16 h10 = __float2bfloat16(v10), h11 = __float2bfloat16(v11);
                size_t p0 = (size_t)row0 * K + col;
                size_t p1 = (size_t)(row0 + 8) * K + col;
                { __nv_bfloat162 x = __halves2bfloat162(h00, h01);
                  *(uint32_t*)(Chi + p0) = *(uint32_t*)&x; }
                { __nv_bfloat162 x = __halves2bfloat162(h10, h11);
                  *(uint32_t*)(Chi + p1) = *(uint32_t*)&x; }
                *(uint32_t*)(Clo + p0) = bfpack2(v00 - __bfloat162float(h00), v01 - __bfloat162float(h01));
                *(uint32_t*)(Clo + p1) = bfpack2(v10 - __bfloat162float(h10), v11 - __bfloat162float(h11));
            }
        }
    }
}

// ---------------------------------------------------------------------------
// MVN epilogue
// ---------------------------------------------------------------------------
__device__ __forceinline__ int triu_idx(int r, int c) {
    return r * (15 - r) / 2 + (c - r - 1);
}

__global__ __launch_bounds__(256)
void mvn_epilogue(const float* __restrict__ lv,
                  float* __restrict__ prec,
                  float* __restrict__ Dout,
                  float* __restrict__ Tout)
{
    constexpr int GP = 4;
    __shared__ float s_eta[GP][E_DIM];
    __shared__ float s_d[GP][O_DIM];
    __shared__ float s_dinv[GP][O_DIM];

    const int g = threadIdx.x >> 6;
    const int t = threadIdx.x & 63;
    const size_t bh = (size_t)blockIdx.x * GP + g;

    if (t < E_DIM) s_eta[g][t] = lv[bh * E_DIM + t];
    __syncthreads();
    if (t < O_DIM) {
        float d = expf(0.5f * s_eta[g][t]);
        s_d[g][t] = d;
        s_dinv[g][t] = 1.f / d;
    }
    __syncthreads();

    const int i = t >> 3, k = t & 7;
    const float* e = s_eta[g];
    const float* dinv = s_dinv[g];

    float tv = (i == k) ? 1.f : ((i < k) ? e[O_DIM + triu_idx(i, k)] : 0.f);
    float dv = (i == k) ? s_d[g][i] : 0.f;
    float s = 0.f;
#pragma unroll
    for (int j = 0; j < O_DIM; j++) {
        float tji = (j == i) ? 1.f : ((j < i) ? e[O_DIM + triu_idx(j, i)] : 0.f);
        float tjk = (j == k) ? 1.f : ((j < k) ? e[O_DIM + triu_idx(j, k)] : 0.f);
        s = fmaf(tji * tjk, dinv[j], s);
    }

    const size_t base = bh * (O_DIM * O_DIM) + t;
    prec[base] = s;
    Dout[base] = dv;
    Tout[base] = tv;
}

// ---------------------------------------------------------------------------
// Launch
// ---------------------------------------------------------------------------
extern "C" void kernel_launch(void* const* d_in, const int* in_sizes, int n_in,
                              void* d_out, int out_size)
{
    const float* z  = (const float*)d_in[0];
    const float* W1 = (const float*)d_in[1];
    const float* b1 = (const float*)d_in[2];
    const float* W2 = (const float*)d_in[3];
    const float* b2 = (const float*)d_in[4];
    const float* Wm = (const float*)d_in[5];
    const float* bm = (const float*)d_in[6];
    const float* Wv = (const float*)d_in[7];
    const float* bv = (const float*)d_in[8];

    float* out = (float*)d_out;
    const size_t n_means = (size_t)BATCH * FH * O_DIM;
    const size_t n_mat   = (size_t)BATCH * FH * O_DIM * O_DIM;
    float* means = out;
    float* prec  = out + n_means;
    float* Dout  = prec + n_mat;
    float* Tout  = Dout + n_mat;

    __nv_bfloat16 *zhi, *zlo, *ihi, *ilo, *hhi, *hlo;
    __nv_bfloat16 *w1hi, *w1lo, *w2hi, *w2lo, *wmhi, *wmlo, *wvhi, *wvlo;
    float* lv;
    cudaGetSymbolAddress((void**)&zhi, g_zhi);   cudaGetSymbolAddress((void**)&zlo, g_zlo);
    cudaGetSymbolAddress((void**)&ihi, g_ihi);   cudaGetSymbolAddress((void**)&ilo, g_ilo);
    cudaGetSymbolAddress((void**)&hhi, g_hhi);   cudaGetSymbolAddress((void**)&hlo, g_hlo);
    cudaGetSymbolAddress((void**)&w1hi, g_w1hi); cudaGetSymbolAddress((void**)&w1lo, g_w1lo);
    cudaGetSymbolAddress((void**)&w2hi, g_w2hi); cudaGetSymbolAddress((void**)&w2lo, g_w2lo);
    cudaGetSymbolAddress((void**)&wmhi, g_wmhi); cudaGetSymbolAddress((void**)&wmlo, g_wmlo);
    cudaGetSymbolAddress((void**)&wvhi, g_wvhi); cudaGetSymbolAddress((void**)&wvlo, g_wvlo);
    cudaGetSymbolAddress((void**)&lv, g_lv);

    const int SMEM_BYTES = 2 * 40960 + 512;   // 82432
    cudaFuncSetAttribute((void*)gemm_mma<true, 1>,  cudaFuncAttributeMaxDynamicSharedMemorySize, SMEM_BYTES);
    cudaFuncSetAttribute((void*)gemm_mma<false, 1>, cudaFuncAttributeMaxDynamicSharedMemorySize, SMEM_BYTES);
    cudaFuncSetAttribute((void*)gemm_mma<false, 0>, cudaFuncAttributeMaxDynamicSharedMemorySize, SMEM_BYTES);

    // converts
    split_act<<<(BATCH * HID / 4) / 256, 256>>>(z, zhi, zlo);
    split_w<<<dim3(HID / 32, HID / 32), 256>>>(W1, w1hi, w1lo, HID, HID);
    split_w<<<dim3(HID / 32, HID / 32), 256>>>(W2, w2hi, w2lo, HID, HID);
    split_w<<<dim3(NM  / 32, HID / 32), 256>>>(Wm, wmhi, wmlo, HID, NM);
    split_w<<<dim3(NV  / 32, HID / 32), 256>>>(Wv, wvhi, wvlo, HID, NV);

    // GEMM chain (CTA 128x128)
    gemm_mma<true, 1><<<dim3(HID / 128, BATCH / 128), 128, SMEM_BYTES>>>(
        HID, zhi, zlo, w1hi, w1lo, b1, nullptr, ihi, ilo);
    gemm_mma<false, 1><<<dim3(HID / 128, BATCH / 128), 128, SMEM_BYTES>>>(
        HID, ihi, ilo, w2hi, w2lo, b2, nullptr, hhi, hlo);
    gemm_mma<false, 0><<<dim3(NM / 128, BATCH / 128), 128, SMEM_BYTES>>>(
        NM, hhi, hlo, wmhi, wmlo, bm, means, nullptr, nullptr);
    gemm_mma<false, 0><<<dim3(NV / 128, BATCH / 128), 128, SMEM_BYTES>>>(
        NV, hhi, hlo, wvhi, wvlo, bv, lv, nullptr, nullptr);

    mvn_epilogue<<<(BATCH * FH) / 4, 256>>>(lv, prec, Dout, Tout);
}

// round 6
// speedup vs baseline: 1.1199x; 1.1199x over previous
#include <cuda_runtime.h>
#include <cuda_bf16.h>
#include <math.h>
#include <stdint.h>

#define BATCH 8192
#define HID   1024
#define FH    96
#define O_DIM 8
#define E_DIM 36
#define NM    768
#define NV    3456

// ---------------------------------------------------------------------------
// Device scratch (allocation-free per harness rules)
// ---------------------------------------------------------------------------
__device__ __nv_bfloat16 g_zhi[(size_t)BATCH * HID];
__device__ __nv_bfloat16 g_zlo[(size_t)BATCH * HID];
__device__ __nv_bfloat16 g_ihi[(size_t)BATCH * HID];
__device__ __nv_bfloat16 g_ilo[(size_t)BATCH * HID];
__device__ __nv_bfloat16 g_hhi[(size_t)BATCH * HID];
__device__ __nv_bfloat16 g_hlo[(size_t)BATCH * HID];
__device__ __nv_bfloat16 g_w1hi[(size_t)HID * HID];
__device__ __nv_bfloat16 g_w1lo[(size_t)HID * HID];
__device__ __nv_bfloat16 g_w2hi[(size_t)HID * HID];
__device__ __nv_bfloat16 g_w2lo[(size_t)HID * HID];
__device__ __nv_bfloat16 g_wmhi[(size_t)NM * HID];
__device__ __nv_bfloat16 g_wmlo[(size_t)NM * HID];
__device__ __nv_bfloat16 g_wvhi[(size_t)NV * HID];
__device__ __nv_bfloat16 g_wvlo[(size_t)NV * HID];
__device__ float         g_lv[(size_t)BATCH * NV];

// ---------------------------------------------------------------------------
// helpers
// ---------------------------------------------------------------------------
__device__ __forceinline__ uint32_t smem_u32(const void* p) {
    uint32_t a;
    asm("{ .reg .u64 t; cvta.to.shared.u64 t, %1; cvt.u32.u64 %0, t; }" : "=r"(a) : "l"(p));
    return a;
}

__device__ __forceinline__ void cp16(uint32_t dst, const void* src) {
    asm volatile("cp.async.cg.shared.global [%0], [%1], 16;" :: "r"(dst), "l"(src));
}
#define CP_COMMIT() asm volatile("cp.async.commit_group;" ::: "memory")
#define CP_WAIT0()  asm volatile("cp.async.wait_group 0;"  ::: "memory")
#define CP_WAIT1()  asm volatile("cp.async.wait_group 1;"  ::: "memory")

__device__ __forceinline__ void ldsm4(uint32_t* r, uint32_t addr) {
    asm volatile("ldmatrix.sync.aligned.m8n8.x4.shared.b16 {%0,%1,%2,%3}, [%4];"
        : "=r"(r[0]), "=r"(r[1]), "=r"(r[2]), "=r"(r[3]) : "r"(addr));
}

__device__ __forceinline__ void mma16816(float* d, const uint32_t* a, const uint32_t* b)
{
    asm volatile(
        "mma.sync.aligned.m16n8k16.row.col.f32.bf16.bf16.f32 "
        "{%0,%1,%2,%3},{%4,%5,%6,%7},{%8,%9},{%0,%1,%2,%3};\n"
        : "+f"(d[0]), "+f"(d[1]), "+f"(d[2]), "+f"(d[3])
        : "r"(a[0]), "r"(a[1]), "r"(a[2]), "r"(a[3]), "r"(b[0]), "r"(b[1]));
}

__device__ __forceinline__ uint32_t bfpack2(float a, float b) {
    __nv_bfloat162 t = __halves2bfloat162(__float2bfloat16(a), __float2bfloat16(b));
    return *reinterpret_cast<uint32_t*>(&t);
}

// ---------------------------------------------------------------------------
// split_act: fp32 [n] -> hi bf16 [n], lo bf16 [n]
// ---------------------------------------------------------------------------
__global__ __launch_bounds__(256)
void split_act(const float* __restrict__ x,
               __nv_bfloat16* __restrict__ hi, __nv_bfloat16* __restrict__ lo)
{
    size_t idx = ((size_t)blockIdx.x * blockDim.x + threadIdx.x) * 4;
    float4 v = *(const float4*)(x + idx);
    __nv_bfloat16 h0 = __float2bfloat16(v.x), h1 = __float2bfloat16(v.y);
    __nv_bfloat16 h2 = __float2bfloat16(v.z), h3 = __float2bfloat16(v.w);
    uint2 hp, lp;
    { __nv_bfloat162 a = __halves2bfloat162(h0, h1), b = __halves2bfloat162(h2, h3);
      hp.x = *(uint32_t*)&a; hp.y = *(uint32_t*)&b; }
    lp.x = bfpack2(v.x - __bfloat162float(h0), v.y - __bfloat162float(h1));
    lp.y = bfpack2(v.z - __bfloat162float(h2), v.w - __bfloat162float(h3));
    *(uint2*)(hi + idx) = hp;
    *(uint2*)(lo + idx) = lp;
}

// ---------------------------------------------------------------------------
// split_w: W fp32 [K, N] -> Wt hi/lo bf16 [N, K] (transposed + split)
// ---------------------------------------------------------------------------
__global__ __launch_bounds__(256)
void split_w(const float* __restrict__ W,
             __nv_bfloat16* __restrict__ Whi, __nv_bfloat16* __restrict__ Wlo,
             int K, int N)
{
    __shared__ float tile[32][33];
    const int k0 = blockIdx.y * 32, n0 = blockIdx.x * 32;
    const int tx = threadIdx.x & 31, ty = threadIdx.x >> 5;
#pragma unroll
    for (int r = ty; r < 32; r += 8)
        tile[r][tx] = W[(size_t)(k0 + r) * N + n0 + tx];
    __syncthreads();
#pragma unroll
    for (int i = threadIdx.x; i < 32 * 16; i += 256) {
        int nl = i >> 4, kp = i & 15;
        float a = tile[2 * kp][nl], b = tile[2 * kp + 1][nl];
        __nv_bfloat16 ha = __float2bfloat16(a), hb = __float2bfloat16(b);
        size_t base = (size_t)(n0 + nl) * K + k0 + 2 * kp;
        *(uint32_t*)(Whi + base) = bfpack2(a, b);
        *(uint32_t*)(Wlo + base) = bfpack2(a - __bfloat162float(ha), b - __bfloat162float(hb));
    }
}

// ---------------------------------------------------------------------------
// bf16x3 GEMM, pre-split inputs: C[M,N] = act(A @ Bt^T + bias)
// CTA 256x128, BK=16, 8 warps (4M x 2N), warp tile 64x64.
// 3-stage cp.async pipeline, ldmatrix fragment loads.
// OUTMODE 0: fp32 out Cf. OUTMODE 1: bf16 hi/lo out (Chi/Clo).
// ---------------------------------------------------------------------------
template <bool SILU, int OUTMODE>
__global__ __launch_bounds__(256, 1)
void gemm_mma(int N,
              const __nv_bfloat16* __restrict__ Ahi, const __nv_bfloat16* __restrict__ Alo,
              const __nv_bfloat16* __restrict__ Bthi, const __nv_bfloat16* __restrict__ Btlo,
              const float* __restrict__ bias,
              float* __restrict__ Cf,
              __nv_bfloat16* __restrict__ Chi, __nv_bfloat16* __restrict__ Clo)
{
    constexpr int K = HID;
    constexpr int NITER = K / 16;          // 64 k-steps
    constexpr int RS = 48;                 // 16 bf16 = 32B + 16B pad
    constexpr int SA_HI = 0;
    constexpr int SA_LO = 256 * RS;        // 12288
    constexpr int SB_HI = 2 * 256 * RS;    // 24576
    constexpr int SB_LO = SB_HI + 128 * RS;// 30720
    constexpr int STAGE = SB_LO + 128 * RS;// 36864
    constexpr int BIASOFF = 3 * STAGE;     // 110592

    extern __shared__ __align__(128) char smem[];
    const uint32_t sb = smem_u32(smem);
    float* sBias = (float*)(smem + BIASOFF);

    const int tid  = threadIdx.x;
    const int lane = tid & 31;
    const int wid  = tid >> 5;
    const int g = lane >> 2;               // 0..7
    const int t = lane & 3;                // 0..3
    const int m0 = (wid & 3) * 64;         // 4 warps along M
    const int n0 = (wid >> 2) * 64;        // 2 warps along N

    const int blockM = blockIdx.y * 256;
    const int blockN = blockIdx.x * 128;

    if (tid < 128) sBias[tid] = bias[blockN + tid];

    // ldmatrix per-lane address offsets (within a stage buffer)
    const uint32_t aoff = (uint32_t)(m0 + (lane & 15)) * RS + (uint32_t)(lane >> 4) * 16;
    const uint32_t boff = (uint32_t)(n0 + ((lane >> 4) << 3) + (lane & 7)) * RS
                        + (uint32_t)((lane >> 3) & 1) * 16;

    const __nv_bfloat16* Ahi_b = Ahi + (size_t)blockM * K;
    const __nv_bfloat16* Alo_b = Alo + (size_t)blockM * K;
    const __nv_bfloat16* Bhi_b = Bthi + (size_t)blockN * K;
    const __nv_bfloat16* Blo_b = Btlo + (size_t)blockN * K;

    auto load_stage = [&](int s) {
        const int k0 = s * 16;
        const uint32_t buf = sb + (s % 3) * STAGE;
#pragma unroll
        for (int j = 0; j < 2; j++) {
            const int idx = tid + 256 * j;
            const int row = idx >> 1, ch = idx & 1;
            const size_t goff = (size_t)row * K + k0 + ch * 8;
            const uint32_t soff = row * RS + ch * 16;
            cp16(buf + SA_HI + soff, Ahi_b + goff);
            cp16(buf + SA_LO + soff, Alo_b + goff);
        }
        {
            const int row = tid >> 1, ch = tid & 1;
            const size_t goff = (size_t)row * K + k0 + ch * 8;
            const uint32_t soff = row * RS + ch * 16;
            cp16(buf + SB_HI + soff, Bhi_b + goff);
            cp16(buf + SB_LO + soff, Blo_b + goff);
        }
    };

    float acc[4][8][4];
#pragma unroll
    for (int mt = 0; mt < 4; mt++)
#pragma unroll
        for (int nt = 0; nt < 8; nt++)
#pragma unroll
            for (int c = 0; c < 4; c++) acc[mt][nt][c] = 0.f;

    load_stage(0); CP_COMMIT();
    load_stage(1); CP_COMMIT();

    for (int it = 0; it < NITER; ++it) {
        if (it == NITER - 1) { CP_WAIT0(); } else { CP_WAIT1(); }
        __syncthreads();
        if (it + 2 < NITER) { load_stage(it + 2); CP_COMMIT(); }

        const uint32_t buf = sb + (it % 3) * STAGE;
        const uint32_t aHi = buf + SA_HI + aoff;
        const uint32_t aLo = buf + SA_LO + aoff;
        const uint32_t bHi = buf + SB_HI + boff;
        const uint32_t bLo = buf + SB_LO + boff;

        uint32_t fAhi[4][4], fAlo[4][4], fB[8][2];
#pragma unroll
        for (int mt = 0; mt < 4; mt++) {
            ldsm4(fAhi[mt], aHi + mt * 16 * RS);
            ldsm4(fAlo[mt], aLo + mt * 16 * RS);
        }
#pragma unroll
        for (int nt = 0; nt < 8; nt += 2)
            ldsm4(&fB[nt][0], bHi + nt * 8 * RS);

        // pass 1: hi*hi ; pass 2: loA*hiB
#pragma unroll
        for (int mt = 0; mt < 4; mt++)
#pragma unroll
            for (int nt = 0; nt < 8; nt++) {
                mma16816(acc[mt][nt], fAhi[mt], fB[nt]);
                mma16816(acc[mt][nt], fAlo[mt], fB[nt]);
            }
        // reload B lo, pass 3: hiA*loB
#pragma unroll
        for (int nt = 0; nt < 8; nt += 2)
            ldsm4(&fB[nt][0], bLo + nt * 8 * RS);
#pragma unroll
        for (int mt = 0; mt < 4; mt++)
#pragma unroll
            for (int nt = 0; nt < 8; nt++)
                mma16816(acc[mt][nt], fAhi[mt], fB[nt]);
    }

    // epilogue
#pragma unroll
    for (int mt = 0; mt < 4; mt++) {
        const int row0 = blockM + m0 + mt * 16 + g;
#pragma unroll
        for (int nt = 0; nt < 8; nt++) {
            const int coll = n0 + nt * 8 + 2 * t;
            const int col  = blockN + coll;
            const float bv0 = sBias[coll], bv1 = sBias[coll + 1];
            float v00 = acc[mt][nt][0] + bv0, v01 = acc[mt][nt][1] + bv1;
            float v10 = acc[mt][nt][2] + bv0, v11 = acc[mt][nt][3] + bv1;
            if (SILU) {
                v00 = v00 / (1.f + expf(-v00));
                v01 = v01 / (1.f + expf(-v01));
                v10 = v10 / (1.f + expf(-v10));
                v11 = v11 / (1.f + expf(-v11));
            }
            if (OUTMODE == 0) {
                float2 a = {v00, v01}, b = {v10, v11};
                *(float2*)(Cf + (size_t)row0 * N + col)       = a;
                *(float2*)(Cf + (size_t)(row0 + 8) * N + col) = b;
            } else {
                __nv_bfloat16 h00 = __float2bfloat16(v00), h01 = __float2bfloat16(v01);
                __nv_bfloat16 h10 = __float2bfloat16(v10), h11 = __float2bfloat16(v11);
                size_t p0 = (size_t)row0 * K + col;
                size_t p1 = (size_t)(row0 + 8) * K + col;
                { __nv_bfloat162 x = __halves2bfloat162(h00, h01);
                  *(uint32_t*)(Chi + p0) = *(uint32_t*)&x; }
                { __nv_bfloat162 x = __halves2bfloat162(h10, h11);
                  *(uint32_t*)(Chi + p1) = *(uint32_t*)&x; }
                *(uint32_t*)(Clo + p0) = bfpack2(v00 - __bfloat162float(h00), v01 - __bfloat162float(h01));
                *(uint32_t*)(Clo + p1) = bfpack2(v10 - __bfloat162float(h10), v11 - __bfloat162float(h11));
            }
        }
    }
}

// ---------------------------------------------------------------------------
// MVN epilogue
// ---------------------------------------------------------------------------
__device__ __forceinline__ int triu_idx(int r, int c) {
    return r * (15 - r) / 2 + (c - r - 1);
}

__global__ __launch_bounds__(256)
void mvn_epilogue(const float* __restrict__ lv,
                  float* __restrict__ prec,
                  float* __restrict__ Dout,
                  float* __restrict__ Tout)
{
    constexpr int GP = 4;
    __shared__ float s_eta[GP][E_DIM];
    __shared__ float s_d[GP][O_DIM];
    __shared__ float s_dinv[GP][O_DIM];

    const int g = threadIdx.x >> 6;
    const int t = threadIdx.x & 63;
    const size_t bh = (size_t)blockIdx.x * GP + g;

    if (t < E_DIM) s_eta[g][t] = lv[bh * E_DIM + t];
    __syncthreads();
    if (t < O_DIM) {
        float d = expf(0.5f * s_eta[g][t]);
        s_d[g][t] = d;
        s_dinv[g][t] = 1.f / d;
    }
    __syncthreads();

    const int i = t >> 3, k = t & 7;
    const float* e = s_eta[g];
    const float* dinv = s_dinv[g];

    float tv = (i == k) ? 1.f : ((i < k) ? e[O_DIM + triu_idx(i, k)] : 0.f);
    float dv = (i == k) ? s_d[g][i] : 0.f;
    float s = 0.f;
#pragma unroll
    for (int j = 0; j < O_DIM; j++) {
        float tji = (j == i) ? 1.f : ((j < i) ? e[O_DIM + triu_idx(j, i)] : 0.f);
        float tjk = (j == k) ? 1.f : ((j < k) ? e[O_DIM + triu_idx(j, k)] : 0.f);
        s = fmaf(tji * tjk, dinv[j], s);
    }

    const size_t base = bh * (O_DIM * O_DIM) + t;
    prec[base] = s;
    Dout[base] = dv;
    Tout[base] = tv;
}

// ---------------------------------------------------------------------------
// Launch
// ---------------------------------------------------------------------------
extern "C" void kernel_launch(void* const* d_in, const int* in_sizes, int n_in,
                              void* d_out, int out_size)
{
    const float* z  = (const float*)d_in[0];
    const float* W1 = (const float*)d_in[1];
    const float* b1 = (const float*)d_in[2];
    const float* W2 = (const float*)d_in[3];
    const float* b2 = (const float*)d_in[4];
    const float* Wm = (const float*)d_in[5];
    const float* bm = (const float*)d_in[6];
    const float* Wv = (const float*)d_in[7];
    const float* bv = (const float*)d_in[8];

    float* out = (float*)d_out;
    const size_t n_means = (size_t)BATCH * FH * O_DIM;
    const size_t n_mat   = (size_t)BATCH * FH * O_DIM * O_DIM;
    float* means = out;
    float* prec  = out + n_means;
    float* Dout  = prec + n_mat;
    float* Tout  = Dout + n_mat;

    __nv_bfloat16 *zhi, *zlo, *ihi, *ilo, *hhi, *hlo;
    __nv_bfloat16 *w1hi, *w1lo, *w2hi, *w2lo, *wmhi, *wmlo, *wvhi, *wvlo;
    float* lv;
    cudaGetSymbolAddress((void**)&zhi, g_zhi);   cudaGetSymbolAddress((void**)&zlo, g_zlo);
    cudaGetSymbolAddress((void**)&ihi, g_ihi);   cudaGetSymbolAddress((void**)&ilo, g_ilo);
    cudaGetSymbolAddress((void**)&hhi, g_hhi);   cudaGetSymbolAddress((void**)&hlo, g_hlo);
    cudaGetSymbolAddress((void**)&w1hi, g_w1hi); cudaGetSymbolAddress((void**)&w1lo, g_w1lo);
    cudaGetSymbolAddress((void**)&w2hi, g_w2hi); cudaGetSymbolAddress((void**)&w2lo, g_w2lo);
    cudaGetSymbolAddress((void**)&wmhi, g_wmhi); cudaGetSymbolAddress((void**)&wmlo, g_wmlo);
    cudaGetSymbolAddress((void**)&wvhi, g_wvhi); cudaGetSymbolAddress((void**)&wvlo, g_wvlo);
    cudaGetSymbolAddress((void**)&lv, g_lv);

    const int SMEM_BYTES = 3 * 36864 + 512;   // 111104
    cudaFuncSetAttribute((void*)gemm_mma<true, 1>,  cudaFuncAttributeMaxDynamicSharedMemorySize, SMEM_BYTES);
    cudaFuncSetAttribute((void*)gemm_mma<false, 1>, cudaFuncAttributeMaxDynamicSharedMemorySize, SMEM_BYTES);
    cudaFuncSetAttribute((void*)gemm_mma<false, 0>, cudaFuncAttributeMaxDynamicSharedMemorySize, SMEM_BYTES);

    // converts
    split_act<<<(BATCH * HID / 4) / 256, 256>>>(z, zhi, zlo);
    split_w<<<dim3(HID / 32, HID / 32), 256>>>(W1, w1hi, w1lo, HID, HID);
    split_w<<<dim3(HID / 32, HID / 32), 256>>>(W2, w2hi, w2lo, HID, HID);
    split_w<<<dim3(NM  / 32, HID / 32), 256>>>(Wm, wmhi, wmlo, HID, NM);
    split_w<<<dim3(NV  / 32, HID / 32), 256>>>(Wv, wvhi, wvlo, HID, NV);

    // GEMM chain (CTA 256x128)
    gemm_mma<true, 1><<<dim3(HID / 128, BATCH / 256), 256, SMEM_BYTES>>>(
        HID, zhi, zlo, w1hi, w1lo, b1, nullptr, ihi, ilo);
    gemm_mma<false, 1><<<dim3(HID / 128, BATCH / 256), 256, SMEM_BYTES>>>(
        HID, ihi, ilo, w2hi, w2lo, b2, nullptr, hhi, hlo);
    gemm_mma<false, 0><<<dim3(NM / 128, BATCH / 256), 256, SMEM_BYTES>>>(
        NM, hhi, hlo, wmhi, wmlo, bm, means, nullptr, nullptr);
    gemm_mma<false, 0><<<dim3(NV / 128, BATCH / 256), 256, SMEM_BYTES>>>(
        NV, hhi, hlo, wvhi, wvlo, bv, lv, nullptr, nullptr);

    mvn_epilogue<<<(BATCH * FH) / 4, 256>>>(lv, prec, Dout, Tout);
}

// round 7
// speedup vs baseline: 1.1941x; 1.0663x over previous
#include <cuda_runtime.h>
#include <cuda_bf16.h>
#include <math.h>
#include <stdint.h>

#define BATCH 8192
#define HID   1024
#define FH    96
#define O_DIM 8
#define E_DIM 36
#define NM    768
#define NV    3456
#define NCAT  (NM + NV)     // 4224

// ---------------------------------------------------------------------------
// Device scratch (allocation-free per harness rules)
// ---------------------------------------------------------------------------
__device__ __nv_bfloat16 g_zhi[(size_t)BATCH * HID];
__device__ __nv_bfloat16 g_zlo[(size_t)BATCH * HID];
__device__ __nv_bfloat16 g_ihi[(size_t)BATCH * HID];
__device__ __nv_bfloat16 g_ilo[(size_t)BATCH * HID];
__device__ __nv_bfloat16 g_hhi[(size_t)BATCH * HID];
__device__ __nv_bfloat16 g_hlo[(size_t)BATCH * HID];
__device__ __nv_bfloat16 g_w1hi[(size_t)HID * HID];
__device__ __nv_bfloat16 g_w1lo[(size_t)HID * HID];
__device__ __nv_bfloat16 g_w2hi[(size_t)HID * HID];
__device__ __nv_bfloat16 g_w2lo[(size_t)HID * HID];
__device__ __nv_bfloat16 g_wchi[(size_t)NCAT * HID];   // [Wm|Wv]^T hi
__device__ __nv_bfloat16 g_wclo[(size_t)NCAT * HID];   // [Wm|Wv]^T lo
__device__ float         g_bcat[NCAT];
__device__ float         g_lv[(size_t)BATCH * NV];

// ---------------------------------------------------------------------------
// helpers
// ---------------------------------------------------------------------------
__device__ __forceinline__ uint32_t smem_u32(const void* p) {
    uint32_t a;
    asm("{ .reg .u64 t; cvta.to.shared.u64 t, %1; cvt.u32.u64 %0, t; }" : "=r"(a) : "l"(p));
    return a;
}

__device__ __forceinline__ void cp16(uint32_t dst, const void* src) {
    asm volatile("cp.async.cg.shared.global [%0], [%1], 16;" :: "r"(dst), "l"(src));
}
#define CP_COMMIT() asm volatile("cp.async.commit_group;" ::: "memory")
#define CP_WAIT0()  asm volatile("cp.async.wait_group 0;"  ::: "memory")
#define CP_WAIT1()  asm volatile("cp.async.wait_group 1;"  ::: "memory")

__device__ __forceinline__ void ldsm4(uint32_t* r, uint32_t addr) {
    asm volatile("ldmatrix.sync.aligned.m8n8.x4.shared.b16 {%0,%1,%2,%3}, [%4];"
        : "=r"(r[0]), "=r"(r[1]), "=r"(r[2]), "=r"(r[3]) : "r"(addr));
}

__device__ __forceinline__ void mma16816(float* d, const uint32_t* a, const uint32_t* b)
{
    asm volatile(
        "mma.sync.aligned.m16n8k16.row.col.f32.bf16.bf16.f32 "
        "{%0,%1,%2,%3},{%4,%5,%6,%7},{%8,%9},{%0,%1,%2,%3};\n"
        : "+f"(d[0]), "+f"(d[1]), "+f"(d[2]), "+f"(d[3])
        : "r"(a[0]), "r"(a[1]), "r"(a[2]), "r"(a[3]), "r"(b[0]), "r"(b[1]));
}

__device__ __forceinline__ uint32_t bfpack2(float a, float b) {
    __nv_bfloat162 t = __halves2bfloat162(__float2bfloat16(a), __float2bfloat16(b));
    return *reinterpret_cast<uint32_t*>(&t);
}

// ---------------------------------------------------------------------------
// split_act: fp32 [n] -> hi bf16 [n], lo bf16 [n]
// ---------------------------------------------------------------------------
__global__ __launch_bounds__(256)
void split_act(const float* __restrict__ x,
               __nv_bfloat16* __restrict__ hi, __nv_bfloat16* __restrict__ lo)
{
    size_t idx = ((size_t)blockIdx.x * blockDim.x + threadIdx.x) * 4;
    float4 v = *(const float4*)(x + idx);
    __nv_bfloat16 h0 = __float2bfloat16(v.x), h1 = __float2bfloat16(v.y);
    __nv_bfloat16 h2 = __float2bfloat16(v.z), h3 = __float2bfloat16(v.w);
    uint2 hp, lp;
    { __nv_bfloat162 a = __halves2bfloat162(h0, h1), b = __halves2bfloat162(h2, h3);
      hp.x = *(uint32_t*)&a; hp.y = *(uint32_t*)&b; }
    lp.x = bfpack2(v.x - __bfloat162float(h0), v.y - __bfloat162float(h1));
    lp.y = bfpack2(v.z - __bfloat162float(h2), v.w - __bfloat162float(h3));
    *(uint2*)(hi + idx) = hp;
    *(uint2*)(lo + idx) = lp;
}

// ---------------------------------------------------------------------------
// split_w: W fp32 [K, N] -> Wt hi/lo bf16 [N, K] (transposed + split)
// ---------------------------------------------------------------------------
__global__ __launch_bounds__(256)
void split_w(const float* __restrict__ W,
             __nv_bfloat16* __restrict__ Whi, __nv_bfloat16* __restrict__ Wlo,
             int K, int N)
{
    __shared__ float tile[32][33];
    const int k0 = blockIdx.y * 32, n0 = blockIdx.x * 32;
    const int tx = threadIdx.x & 31, ty = threadIdx.x >> 5;
#pragma unroll
    for (int r = ty; r < 32; r += 8)
        tile[r][tx] = W[(size_t)(k0 + r) * N + n0 + tx];
    __syncthreads();
#pragma unroll
    for (int i = threadIdx.x; i < 32 * 16; i += 256) {
        int nl = i >> 4, kp = i & 15;
        float a = tile[2 * kp][nl], b = tile[2 * kp + 1][nl];
        __nv_bfloat16 ha = __float2bfloat16(a), hb = __float2bfloat16(b);
        size_t base = (size_t)(n0 + nl) * K + k0 + 2 * kp;
        *(uint32_t*)(Whi + base) = bfpack2(a, b);
        *(uint32_t*)(Wlo + base) = bfpack2(a - __bfloat162float(ha), b - __bfloat162float(hb));
    }
}

// concat biases into g_bcat
__global__ void concat_bias(const float* __restrict__ bm, const float* __restrict__ bv,
                            float* __restrict__ bcat)
{
    int i = blockIdx.x * blockDim.x + threadIdx.x;
    if (i < NCAT) bcat[i] = (i < NM) ? bm[i] : bv[i - NM];
}

// ---------------------------------------------------------------------------
// bf16x3 GEMM, pre-split inputs: C[M,N] = act(A @ Bt^T + bias)
// CTA 256x128, BK=16, 8 warps (4M x 2N), warp tile 64x64.
// 3-stage cp.async pipeline, ldmatrix, independent MMA sweeps (no RAW pairs).
// OUTMODE 1: bf16 hi/lo out (Chi/Clo), N must be HID.
// OUTMODE 2: dual fp32 out: cols [0,NM) -> Cf0 (stride NM), [NM,NCAT) -> Cf1 (stride NV).
// ---------------------------------------------------------------------------
template <bool SILU, int OUTMODE>
__global__ __launch_bounds__(256, 1)
void gemm_mma(const __nv_bfloat16* __restrict__ Ahi, const __nv_bfloat16* __restrict__ Alo,
              const __nv_bfloat16* __restrict__ Bthi, const __nv_bfloat16* __restrict__ Btlo,
              const float* __restrict__ bias,
              float* __restrict__ Cf0, float* __restrict__ Cf1,
              __nv_bfloat16* __restrict__ Chi, __nv_bfloat16* __restrict__ Clo)
{
    constexpr int K = HID;
    constexpr int NITER = K / 16;          // 64 k-steps
    constexpr int RS = 48;                 // 16 bf16 = 32B + 16B pad
    constexpr int SA_HI = 0;
    constexpr int SA_LO = 256 * RS;        // 12288
    constexpr int SB_HI = 2 * 256 * RS;    // 24576
    constexpr int SB_LO = SB_HI + 128 * RS;// 30720
    constexpr int STAGE = SB_LO + 128 * RS;// 36864
    constexpr int BIASOFF = 3 * STAGE;     // 110592

    extern __shared__ __align__(128) char smem[];
    const uint32_t sb = smem_u32(smem);
    float* sBias = (float*)(smem + BIASOFF);

    const int tid  = threadIdx.x;
    const int lane = tid & 31;
    const int wid  = tid >> 5;
    const int g = lane >> 2;               // 0..7
    const int t = lane & 3;                // 0..3
    const int m0 = (wid & 3) * 64;         // 4 warps along M
    const int n0 = (wid >> 2) * 64;        // 2 warps along N

    const int blockM = blockIdx.y * 256;
    const int blockN = blockIdx.x * 128;

    if (tid < 128) sBias[tid] = bias[blockN + tid];

    // ldmatrix per-lane address offsets (within a stage buffer)
    const uint32_t aoff = (uint32_t)(m0 + (lane & 15)) * RS + (uint32_t)(lane >> 4) * 16;
    const uint32_t boff = (uint32_t)(n0 + ((lane >> 4) << 3) + (lane & 7)) * RS
                        + (uint32_t)((lane >> 3) & 1) * 16;

    const __nv_bfloat16* Ahi_b = Ahi + (size_t)blockM * K;
    const __nv_bfloat16* Alo_b = Alo + (size_t)blockM * K;
    const __nv_bfloat16* Bhi_b = Bthi + (size_t)blockN * K;
    const __nv_bfloat16* Blo_b = Btlo + (size_t)blockN * K;

    auto load_stage = [&](int s) {
        const int k0 = s * 16;
        const uint32_t buf = sb + (s % 3) * STAGE;
#pragma unroll
        for (int j = 0; j < 2; j++) {
            const int idx = tid + 256 * j;
            const int row = idx >> 1, ch = idx & 1;
            const size_t goff = (size_t)row * K + k0 + ch * 8;
            const uint32_t soff = row * RS + ch * 16;
            cp16(buf + SA_HI + soff, Ahi_b + goff);
            cp16(buf + SA_LO + soff, Alo_b + goff);
        }
        {
            const int row = tid >> 1, ch = tid & 1;
            const size_t goff = (size_t)row * K + k0 + ch * 8;
            const uint32_t soff = row * RS + ch * 16;
            cp16(buf + SB_HI + soff, Bhi_b + goff);
            cp16(buf + SB_LO + soff, Blo_b + goff);
        }
    };

    float acc[4][8][4];
#pragma unroll
    for (int mt = 0; mt < 4; mt++)
#pragma unroll
        for (int nt = 0; nt < 8; nt++)
#pragma unroll
            for (int c = 0; c < 4; c++) acc[mt][nt][c] = 0.f;

    load_stage(0); CP_COMMIT();
    load_stage(1); CP_COMMIT();

    for (int it = 0; it < NITER; ++it) {
        if (it == NITER - 1) { CP_WAIT0(); } else { CP_WAIT1(); }
        __syncthreads();
        if (it + 2 < NITER) { load_stage(it + 2); CP_COMMIT(); }

        const uint32_t buf = sb + (it % 3) * STAGE;
        const uint32_t aHi = buf + SA_HI + aoff;
        const uint32_t aLo = buf + SA_LO + aoff;
        const uint32_t bHi = buf + SB_HI + boff;
        const uint32_t bLo = buf + SB_LO + boff;

        // issue ALL fragment loads up front (independent LDSMs, pipelined)
        uint32_t fAhi[4][4], fAlo[4][4], fBhi[8][2], fBlo[8][2];
#pragma unroll
        for (int mt = 0; mt < 4; mt++) {
            ldsm4(fAhi[mt], aHi + mt * 16 * RS);
            ldsm4(fAlo[mt], aLo + mt * 16 * RS);
        }
#pragma unroll
        for (int nt = 0; nt < 8; nt += 2) {
            ldsm4(&fBhi[nt][0], bHi + nt * 8 * RS);
            ldsm4(&fBlo[nt][0], bLo + nt * 8 * RS);
        }

        // three INDEPENDENT sweeps: each acc tile touched 32 MMAs apart
#pragma unroll
        for (int mt = 0; mt < 4; mt++)
#pragma unroll
            for (int nt = 0; nt < 8; nt++)
                mma16816(acc[mt][nt], fAhi[mt], fBhi[nt]);
#pragma unroll
        for (int mt = 0; mt < 4; mt++)
#pragma unroll
            for (int nt = 0; nt < 8; nt++)
                mma16816(acc[mt][nt], fAlo[mt], fBhi[nt]);
#pragma unroll
        for (int mt = 0; mt < 4; mt++)
#pragma unroll
            for (int nt = 0; nt < 8; nt++)
                mma16816(acc[mt][nt], fAhi[mt], fBlo[nt]);
    }

    // output target for OUTMODE 2 (block never straddles the NM boundary: 768 % 128 == 0)
    float* Cout = nullptr;
    int cstride = 0, cbase = 0;
    if (OUTMODE == 2) {
        if (blockN < NM) { Cout = Cf0; cstride = NM; cbase = blockN; }
        else             { Cout = Cf1; cstride = NV; cbase = blockN - NM; }
    }

    // epilogue
#pragma unroll
    for (int mt = 0; mt < 4; mt++) {
        const int row0 = blockM + m0 + mt * 16 + g;
#pragma unroll
        for (int nt = 0; nt < 8; nt++) {
            const int coll = n0 + nt * 8 + 2 * t;
            const float bv0 = sBias[coll], bv1 = sBias[coll + 1];
            float v00 = acc[mt][nt][0] + bv0, v01 = acc[mt][nt][1] + bv1;
            float v10 = acc[mt][nt][2] + bv0, v11 = acc[mt][nt][3] + bv1;
            if (SILU) {
                v00 = v00 / (1.f + expf(-v00));
                v01 = v01 / (1.f + expf(-v01));
                v10 = v10 / (1.f + expf(-v10));
                v11 = v11 / (1.f + expf(-v11));
            }
            if (OUTMODE == 2) {
                const int col = cbase + coll;
                float2 a = {v00, v01}, b = {v10, v11};
                *(float2*)(Cout + (size_t)row0 * cstride + col)       = a;
                *(float2*)(Cout + (size_t)(row0 + 8) * cstride + col) = b;
            } else {
                const int col = blockN + coll;
                __nv_bfloat16 h00 = __float2bfloat16(v00), h01 = __float2bfloat16(v01);
                __nv_bfloat16 h10 = __float2bfloat16(v10), h11 = __float2bfloat16(v11);
                size_t p0 = (size_t)row0 * HID + col;
                size_t p1 = (size_t)(row0 + 8) * HID + col;
                { __nv_bfloat162 x = __halves2bfloat162(h00, h01);
                  *(uint32_t*)(Chi + p0) = *(uint32_t*)&x; }
                { __nv_bfloat162 x = __halves2bfloat162(h10, h11);
                  *(uint32_t*)(Chi + p1) = *(uint32_t*)&x; }
                *(uint32_t*)(Clo + p0) = bfpack2(v00 - __bfloat162float(h00), v01 - __bfloat162float(h01));
                *(uint32_t*)(Clo + p1) = bfpack2(v10 - __bfloat162float(h10), v11 - __bfloat162float(h11));
            }
        }
    }
}

// ---------------------------------------------------------------------------
// MVN epilogue
// ---------------------------------------------------------------------------
__device__ __forceinline__ int triu_idx(int r, int c) {
    return r * (15 - r) / 2 + (c - r - 1);
}

__global__ __launch_bounds__(256)
void mvn_epilogue(const float* __restrict__ lv,
                  float* __restrict__ prec,
                  float* __restrict__ Dout,
                  float* __restrict__ Tout)
{
    constexpr int GP = 4;
    __shared__ float s_eta[GP][E_DIM];
    __shared__ float s_d[GP][O_DIM];
    __shared__ float s_dinv[GP][O_DIM];

    const int g = threadIdx.x >> 6;
    const int t = threadIdx.x & 63;
    const size_t bh = (size_t)blockIdx.x * GP + g;

    if (t < E_DIM) s_eta[g][t] = lv[bh * E_DIM + t];
    __syncthreads();
    if (t < O_DIM) {
        float d = expf(0.5f * s_eta[g][t]);
        s_d[g][t] = d;
        s_dinv[g][t] = 1.f / d;
    }
    __syncthreads();

    const int i = t >> 3, k = t & 7;
    const float* e = s_eta[g];
    const float* dinv = s_dinv[g];

    float tv = (i == k) ? 1.f : ((i < k) ? e[O_DIM + triu_idx(i, k)] : 0.f);
    float dv = (i == k) ? s_d[g][i] : 0.f;
    float s = 0.f;
#pragma unroll
    for (int j = 0; j < O_DIM; j++) {
        float tji = (j == i) ? 1.f : ((j < i) ? e[O_DIM + triu_idx(j, i)] : 0.f);
        float tjk = (j == k) ? 1.f : ((j < k) ? e[O_DIM + triu_idx(j, k)] : 0.f);
        s = fmaf(tji * tjk, dinv[j], s);
    }

    const size_t base = bh * (O_DIM * O_DIM) + t;
    prec[base] = s;
    Dout[base] = dv;
    Tout[base] = tv;
}

// ---------------------------------------------------------------------------
// Launch
// ---------------------------------------------------------------------------
extern "C" void kernel_launch(void* const* d_in, const int* in_sizes, int n_in,
                              void* d_out, int out_size)
{
    const float* z  = (const float*)d_in[0];
    const float* W1 = (const float*)d_in[1];
    const float* b1 = (const float*)d_in[2];
    const float* W2 = (const float*)d_in[3];
    const float* b2 = (const float*)d_in[4];
    const float* Wm = (const float*)d_in[5];
    const float* bm = (const float*)d_in[6];
    const float* Wv = (const float*)d_in[7];
    const float* bv = (const float*)d_in[8];

    float* out = (float*)d_out;
    const size_t n_means = (size_t)BATCH * FH * O_DIM;
    const size_t n_mat   = (size_t)BATCH * FH * O_DIM * O_DIM;
    float* means = out;
    float* prec  = out + n_means;
    float* Dout  = prec + n_mat;
    float* Tout  = Dout + n_mat;

    __nv_bfloat16 *zhi, *zlo, *ihi, *ilo, *hhi, *hlo;
    __nv_bfloat16 *w1hi, *w1lo, *w2hi, *w2lo, *wchi, *wclo;
    float *lv, *bcat;
    cudaGetSymbolAddress((void**)&zhi, g_zhi);   cudaGetSymbolAddress((void**)&zlo, g_zlo);
    cudaGetSymbolAddress((void**)&ihi, g_ihi);   cudaGetSymbolAddress((void**)&ilo, g_ilo);
    cudaGetSymbolAddress((void**)&hhi, g_hhi);   cudaGetSymbolAddress((void**)&hlo, g_hlo);
    cudaGetSymbolAddress((void**)&w1hi, g_w1hi); cudaGetSymbolAddress((void**)&w1lo, g_w1lo);
    cudaGetSymbolAddress((void**)&w2hi, g_w2hi); cudaGetSymbolAddress((void**)&w2lo, g_w2lo);
    cudaGetSymbolAddress((void**)&wchi, g_wchi); cudaGetSymbolAddress((void**)&wclo, g_wclo);
    cudaGetSymbolAddress((void**)&bcat, g_bcat);
    cudaGetSymbolAddress((void**)&lv, g_lv);

    const int SMEM_BYTES = 3 * 36864 + 512;   // 111104
    cudaFuncSetAttribute((void*)gemm_mma<true, 1>,  cudaFuncAttributeMaxDynamicSharedMemorySize, SMEM_BYTES);
    cudaFuncSetAttribute((void*)gemm_mma<false, 1>, cudaFuncAttributeMaxDynamicSharedMemorySize, SMEM_BYTES);
    cudaFuncSetAttribute((void*)gemm_mma<false, 2>, cudaFuncAttributeMaxDynamicSharedMemorySize, SMEM_BYTES);

    // converts
    split_act<<<(BATCH * HID / 4) / 256, 256>>>(z, zhi, zlo);
    split_w<<<dim3(HID / 32, HID / 32), 256>>>(W1, w1hi, w1lo, HID, HID);
    split_w<<<dim3(HID / 32, HID / 32), 256>>>(W2, w2hi, w2lo, HID, HID);
    split_w<<<dim3(NM  / 32, HID / 32), 256>>>(Wm, wchi, wclo, HID, NM);
    split_w<<<dim3(NV  / 32, HID / 32), 256>>>(Wv, wchi + (size_t)NM * HID,
                                               wclo + (size_t)NM * HID, HID, NV);
    concat_bias<<<(NCAT + 255) / 256, 256>>>(bm, bv, bcat);

    // GEMM chain (CTA 256x128)
    gemm_mma<true, 1><<<dim3(HID / 128, BATCH / 256), 256, SMEM_BYTES>>>(
        zhi, zlo, w1hi, w1lo, b1, nullptr, nullptr, ihi, ilo);
    gemm_mma<false, 1><<<dim3(HID / 128, BATCH / 256), 256, SMEM_BYTES>>>(
        ihi, ilo, w2hi, w2lo, b2, nullptr, nullptr, hhi, hlo);
    gemm_mma<false, 2><<<dim3(NCAT / 128, BATCH / 256), 256, SMEM_BYTES>>>(
        hhi, hlo, wchi, wclo, bcat, means, lv, nullptr, nullptr);

    mvn_epilogue<<<(BATCH * FH) / 4, 256>>>(lv, prec, Dout, Tout);
}

// round 8
// speedup vs baseline: 1.3364x; 1.1192x over previous
#include <cuda_runtime.h>
#include <cuda_fp16.h>
#include <math.h>
#include <stdint.h>

#define BATCH 8192
#define HID   1024
#define FH    96
#define O_DIM 8
#define E_DIM 36
#define NM    768
#define NV    3456
#define NCAT  (NM + NV)     // 4224

// ---------------------------------------------------------------------------
// Device scratch (allocation-free per harness rules)
// ---------------------------------------------------------------------------
__device__ __half g_zhi[(size_t)BATCH * HID];
__device__ __half g_zlo[(size_t)BATCH * HID];
__device__ __half g_ihi[(size_t)BATCH * HID];
__device__ __half g_ilo[(size_t)BATCH * HID];
__device__ __half g_hhi[(size_t)BATCH * HID];
__device__ __half g_hlo[(size_t)BATCH * HID];
__device__ __half g_w1hi[(size_t)HID * HID];
__device__ __half g_w1lo[(size_t)HID * HID];
__device__ __half g_w2hi[(size_t)HID * HID];
__device__ __half g_w2lo[(size_t)HID * HID];
__device__ __half g_wchi[(size_t)NCAT * HID];   // [Wm|Wv]^T hi
__device__ __half g_wclo[(size_t)NCAT * HID];   // unused by 2-pass GEMM3 (kept for layout)
__device__ float  g_bcat[NCAT];
__device__ float  g_lv[(size_t)BATCH * NV];

// ---------------------------------------------------------------------------
// helpers
// ---------------------------------------------------------------------------
__device__ __forceinline__ uint32_t smem_u32(const void* p) {
    uint32_t a;
    asm("{ .reg .u64 t; cvta.to.shared.u64 t, %1; cvt.u32.u64 %0, t; }" : "=r"(a) : "l"(p));
    return a;
}

__device__ __forceinline__ void cp16(uint32_t dst, const void* src) {
    asm volatile("cp.async.cg.shared.global [%0], [%1], 16;" :: "r"(dst), "l"(src));
}
#define CP_COMMIT() asm volatile("cp.async.commit_group;" ::: "memory")
#define CP_WAIT0()  asm volatile("cp.async.wait_group 0;"  ::: "memory")
#define CP_WAIT1()  asm volatile("cp.async.wait_group 1;"  ::: "memory")

__device__ __forceinline__ void ldsm4(uint32_t* r, uint32_t addr) {
    asm volatile("ldmatrix.sync.aligned.m8n8.x4.shared.b16 {%0,%1,%2,%3}, [%4];"
        : "=r"(r[0]), "=r"(r[1]), "=r"(r[2]), "=r"(r[3]) : "r"(addr));
}

__device__ __forceinline__ void mma16816(float* d, const uint32_t* a, const uint32_t* b)
{
    asm volatile(
        "mma.sync.aligned.m16n8k16.row.col.f32.f16.f16.f32 "
        "{%0,%1,%2,%3},{%4,%5,%6,%7},{%8,%9},{%0,%1,%2,%3};\n"
        : "+f"(d[0]), "+f"(d[1]), "+f"(d[2]), "+f"(d[3])
        : "r"(a[0]), "r"(a[1]), "r"(a[2]), "r"(a[3]), "r"(b[0]), "r"(b[1]));
}

__device__ __forceinline__ uint32_t hpack2(float a, float b) {
    __half2 t = __halves2half2(__float2half_rn(a), __float2half_rn(b));
    return *reinterpret_cast<uint32_t*>(&t);
}

// ---------------------------------------------------------------------------
// split_act: fp32 [n] -> hi fp16 [n], lo fp16 [n]
// ---------------------------------------------------------------------------
__global__ __launch_bounds__(256)
void split_act(const float* __restrict__ x,
               __half* __restrict__ hi, __half* __restrict__ lo)
{
    size_t idx = ((size_t)blockIdx.x * blockDim.x + threadIdx.x) * 4;
    float4 v = *(const float4*)(x + idx);
    __half h0 = __float2half_rn(v.x), h1 = __float2half_rn(v.y);
    __half h2 = __float2half_rn(v.z), h3 = __float2half_rn(v.w);
    uint2 hp, lp;
    { __half2 a = __halves2half2(h0, h1), b = __halves2half2(h2, h3);
      hp.x = *(uint32_t*)&a; hp.y = *(uint32_t*)&b; }
    lp.x = hpack2(v.x - __half2float(h0), v.y - __half2float(h1));
    lp.y = hpack2(v.z - __half2float(h2), v.w - __half2float(h3));
    *(uint2*)(hi + idx) = hp;
    *(uint2*)(lo + idx) = lp;
}

// ---------------------------------------------------------------------------
// split_w: W fp32 [K, N] -> Wt hi/lo fp16 [N, K] (transposed + split)
// ---------------------------------------------------------------------------
__global__ __launch_bounds__(256)
void split_w(const float* __restrict__ W,
             __half* __restrict__ Whi, __half* __restrict__ Wlo,
             int K, int N, int write_lo)
{
    __shared__ float tile[32][33];
    const int k0 = blockIdx.y * 32, n0 = blockIdx.x * 32;
    const int tx = threadIdx.x & 31, ty = threadIdx.x >> 5;
#pragma unroll
    for (int r = ty; r < 32; r += 8)
        tile[r][tx] = W[(size_t)(k0 + r) * N + n0 + tx];
    __syncthreads();
#pragma unroll
    for (int i = threadIdx.x; i < 32 * 16; i += 256) {
        int nl = i >> 4, kp = i & 15;
        float a = tile[2 * kp][nl], b = tile[2 * kp + 1][nl];
        __half ha = __float2half_rn(a), hb = __float2half_rn(b);
        size_t base = (size_t)(n0 + nl) * K + k0 + 2 * kp;
        { __half2 x = __halves2half2(ha, hb);
          *(uint32_t*)(Whi + base) = *(uint32_t*)&x; }
        if (write_lo)
            *(uint32_t*)(Wlo + base) = hpack2(a - __half2float(ha), b - __half2float(hb));
    }
}

// concat biases into g_bcat
__global__ void concat_bias(const float* __restrict__ bm, const float* __restrict__ bv,
                            float* __restrict__ bcat)
{
    int i = blockIdx.x * blockDim.x + threadIdx.x;
    if (i < NCAT) bcat[i] = (i < NM) ? bm[i] : bv[i - NM];
}

// ---------------------------------------------------------------------------
// fp16 split GEMM: C[M,N] = act(A @ Bt^T + bias)
// CTA 256x128, BK=16, 8 warps (4M x 2N), warp tile 64x64.
// 3-stage cp.async pipeline, ldmatrix, independent MMA sweeps.
// PASSES=3: hi*hi + lo*hi + hi*lo.  PASSES=2: hi*hi + lo*hi (B_lo never touched).
// OUTMODE 1: fp16 hi/lo out (Chi/Clo), N must be HID.
// OUTMODE 2: dual fp32 out: cols [0,NM) -> Cf0 (stride NM), [NM,NCAT) -> Cf1 (stride NV).
// ---------------------------------------------------------------------------
template <bool SILU, int OUTMODE, int PASSES>
__global__ __launch_bounds__(256, 1)
void gemm_mma(const __half* __restrict__ Ahi, const __half* __restrict__ Alo,
              const __half* __restrict__ Bthi, const __half* __restrict__ Btlo,
              const float* __restrict__ bias,
              float* __restrict__ Cf0, float* __restrict__ Cf1,
              __half* __restrict__ Chi, __half* __restrict__ Clo)
{
    constexpr int K = HID;
    constexpr int NITER = K / 16;          // 64 k-steps
    constexpr int RS = 48;                 // 16 fp16 = 32B + 16B pad
    constexpr int SA_HI = 0;
    constexpr int SA_LO = 256 * RS;        // 12288
    constexpr int SB_HI = 2 * 256 * RS;    // 24576
    constexpr int SB_LO = SB_HI + 128 * RS;// 30720
    constexpr int STAGE = SB_LO + 128 * RS;// 36864
    constexpr int BIASOFF = 3 * STAGE;     // 110592

    extern __shared__ __align__(128) char smem[];
    const uint32_t sb = smem_u32(smem);
    float* sBias = (float*)(smem + BIASOFF);

    const int tid  = threadIdx.x;
    const int lane = tid & 31;
    const int wid  = tid >> 5;
    const int g = lane >> 2;               // 0..7
    const int t = lane & 3;                // 0..3
    const int m0 = (wid & 3) * 64;         // 4 warps along M
    const int n0 = (wid >> 2) * 64;        // 2 warps along N

    const int blockM = blockIdx.y * 256;
    const int blockN = blockIdx.x * 128;

    if (tid < 128) sBias[tid] = bias[blockN + tid];

    // ldmatrix per-lane address offsets (within a stage buffer)
    const uint32_t aoff = (uint32_t)(m0 + (lane & 15)) * RS + (uint32_t)(lane >> 4) * 16;
    const uint32_t boff = (uint32_t)(n0 + ((lane >> 4) << 3) + (lane & 7)) * RS
                        + (uint32_t)((lane >> 3) & 1) * 16;

    const __half* Ahi_b = Ahi + (size_t)blockM * K;
    const __half* Alo_b = Alo + (size_t)blockM * K;
    const __half* Bhi_b = Bthi + (size_t)blockN * K;
    const __half* Blo_b = (PASSES == 3) ? (Btlo + (size_t)blockN * K) : nullptr;

    auto load_stage = [&](int s) {
        const int k0 = s * 16;
        const uint32_t buf = sb + (s % 3) * STAGE;
#pragma unroll
        for (int j = 0; j < 2; j++) {
            const int idx = tid + 256 * j;
            const int row = idx >> 1, ch = idx & 1;
            const size_t goff = (size_t)row * K + k0 + ch * 8;
            const uint32_t soff = row * RS + ch * 16;
            cp16(buf + SA_HI + soff, Ahi_b + goff);
            cp16(buf + SA_LO + soff, Alo_b + goff);
        }
        {
            const int row = tid >> 1, ch = tid & 1;
            const size_t goff = (size_t)row * K + k0 + ch * 8;
            const uint32_t soff = row * RS + ch * 16;
            cp16(buf + SB_HI + soff, Bhi_b + goff);
            if (PASSES == 3)
                cp16(buf + SB_LO + soff, Blo_b + goff);
        }
    };

    float acc[4][8][4];
#pragma unroll
    for (int mt = 0; mt < 4; mt++)
#pragma unroll
        for (int nt = 0; nt < 8; nt++)
#pragma unroll
            for (int c = 0; c < 4; c++) acc[mt][nt][c] = 0.f;

    load_stage(0); CP_COMMIT();
    load_stage(1); CP_COMMIT();

    for (int it = 0; it < NITER; ++it) {
        if (it == NITER - 1) { CP_WAIT0(); } else { CP_WAIT1(); }
        __syncthreads();
        if (it + 2 < NITER) { load_stage(it + 2); CP_COMMIT(); }

        const uint32_t buf = sb + (it % 3) * STAGE;
        const uint32_t aHi = buf + SA_HI + aoff;
        const uint32_t aLo = buf + SA_LO + aoff;
        const uint32_t bHi = buf + SB_HI + boff;
        const uint32_t bLo = buf + SB_LO + boff;

        uint32_t fAhi[4][4], fAlo[4][4], fBhi[8][2], fBlo[8][2];
#pragma unroll
        for (int mt = 0; mt < 4; mt++) {
            ldsm4(fAhi[mt], aHi + mt * 16 * RS);
            ldsm4(fAlo[mt], aLo + mt * 16 * RS);
        }
#pragma unroll
        for (int nt = 0; nt < 8; nt += 2) {
            ldsm4(&fBhi[nt][0], bHi + nt * 8 * RS);
            if (PASSES == 3)
                ldsm4(&fBlo[nt][0], bLo + nt * 8 * RS);
        }

        // independent sweeps: each acc tile touched 32 MMAs apart
#pragma unroll
        for (int mt = 0; mt < 4; mt++)
#pragma unroll
            for (int nt = 0; nt < 8; nt++)
                mma16816(acc[mt][nt], fAhi[mt], fBhi[nt]);
#pragma unroll
        for (int mt = 0; mt < 4; mt++)
#pragma unroll
            for (int nt = 0; nt < 8; nt++)
                mma16816(acc[mt][nt], fAlo[mt], fBhi[nt]);
        if (PASSES == 3) {
#pragma unroll
            for (int mt = 0; mt < 4; mt++)
#pragma unroll
                for (int nt = 0; nt < 8; nt++)
                    mma16816(acc[mt][nt], fAhi[mt], fBlo[nt]);
        }
    }

    // output target for OUTMODE 2 (block never straddles NM boundary: 768 % 128 == 0)
    float* Cout = nullptr;
    int cstride = 0, cbase = 0;
    if (OUTMODE == 2) {
        if (blockN < NM) { Cout = Cf0; cstride = NM; cbase = blockN; }
        else             { Cout = Cf1; cstride = NV; cbase = blockN - NM; }
    }

    // epilogue
#pragma unroll
    for (int mt = 0; mt < 4; mt++) {
        const int row0 = blockM + m0 + mt * 16 + g;
#pragma unroll
        for (int nt = 0; nt < 8; nt++) {
            const int coll = n0 + nt * 8 + 2 * t;
            const float bv0 = sBias[coll], bv1 = sBias[coll + 1];
            float v00 = acc[mt][nt][0] + bv0, v01 = acc[mt][nt][1] + bv1;
            float v10 = acc[mt][nt][2] + bv0, v11 = acc[mt][nt][3] + bv1;
            if (SILU) {
                v00 = v00 / (1.f + expf(-v00));
                v01 = v01 / (1.f + expf(-v01));
                v10 = v10 / (1.f + expf(-v10));
                v11 = v11 / (1.f + expf(-v11));
            }
            if (OUTMODE == 2) {
                const int col = cbase + coll;
                float2 a = {v00, v01}, b = {v10, v11};
                *(float2*)(Cout + (size_t)row0 * cstride + col)       = a;
                *(float2*)(Cout + (size_t)(row0 + 8) * cstride + col) = b;
            } else {
                const int col = blockN + coll;
                __half h00 = __float2half_rn(v00), h01 = __float2half_rn(v01);
                __half h10 = __float2half_rn(v10), h11 = __float2half_rn(v11);
                size_t p0 = (size_t)row0 * HID + col;
                size_t p1 = (size_t)(row0 + 8) * HID + col;
                { __half2 x = __halves2half2(h00, h01);
                  *(uint32_t*)(Chi + p0) = *(uint32_t*)&x; }
                { __half2 x = __halves2half2(h10, h11);
                  *(uint32_t*)(Chi + p1) = *(uint32_t*)&x; }
                *(uint32_t*)(Clo + p0) = hpack2(v00 - __half2float(h00), v01 - __half2float(h01));
                *(uint32_t*)(Clo + p1) = hpack2(v10 - __half2float(h10), v11 - __half2float(h11));
            }
        }
    }
}

// ---------------------------------------------------------------------------
// MVN epilogue
// ---------------------------------------------------------------------------
__device__ __forceinline__ int triu_idx(int r, int c) {
    return r * (15 - r) / 2 + (c - r - 1);
}

__global__ __launch_bounds__(256)
void mvn_epilogue(const float* __restrict__ lv,
                  float* __restrict__ prec,
                  float* __restrict__ Dout,
                  float* __restrict__ Tout)
{
    constexpr int GP = 4;
    __shared__ float s_eta[GP][E_DIM];
    __shared__ float s_d[GP][O_DIM];
    __shared__ float s_dinv[GP][O_DIM];

    const int g = threadIdx.x >> 6;
    const int t = threadIdx.x & 63;
    const size_t bh = (size_t)blockIdx.x * GP + g;

    if (t < E_DIM) s_eta[g][t] = lv[bh * E_DIM + t];
    __syncthreads();
    if (t < O_DIM) {
        float d = expf(0.5f * s_eta[g][t]);
        s_d[g][t] = d;
        s_dinv[g][t] = 1.f / d;
    }
    __syncthreads();

    const int i = t >> 3, k = t & 7;
    const float* e = s_eta[g];
    const float* dinv = s_dinv[g];

    float tv = (i == k) ? 1.f : ((i < k) ? e[O_DIM + triu_idx(i, k)] : 0.f);
    float dv = (i == k) ? s_d[g][i] : 0.f;
    float s = 0.f;
#pragma unroll
    for (int j = 0; j < O_DIM; j++) {
        float tji = (j == i) ? 1.f : ((j < i) ? e[O_DIM + triu_idx(j, i)] : 0.f);
        float tjk = (j == k) ? 1.f : ((j < k) ? e[O_DIM + triu_idx(j, k)] : 0.f);
        s = fmaf(tji * tjk, dinv[j], s);
    }

    const size_t base = bh * (O_DIM * O_DIM) + t;
    prec[base] = s;
    Dout[base] = dv;
    Tout[base] = tv;
}

// ---------------------------------------------------------------------------
// Launch
// ---------------------------------------------------------------------------
extern "C" void kernel_launch(void* const* d_in, const int* in_sizes, int n_in,
                              void* d_out, int out_size)
{
    const float* z  = (const float*)d_in[0];
    const float* W1 = (const float*)d_in[1];
    const float* b1 = (const float*)d_in[2];
    const float* W2 = (const float*)d_in[3];
    const float* b2 = (const float*)d_in[4];
    const float* Wm = (const float*)d_in[5];
    const float* bm = (const float*)d_in[6];
    const float* Wv = (const float*)d_in[7];
    const float* bv = (const float*)d_in[8];

    float* out = (float*)d_out;
    const size_t n_means = (size_t)BATCH * FH * O_DIM;
    const size_t n_mat   = (size_t)BATCH * FH * O_DIM * O_DIM;
    float* means = out;
    float* prec  = out + n_means;
    float* Dout  = prec + n_mat;
    float* Tout  = Dout + n_mat;

    __half *zhi, *zlo, *ihi, *ilo, *hhi, *hlo;
    __half *w1hi, *w1lo, *w2hi, *w2lo, *wchi, *wclo;
    float *lv, *bcat;
    cudaGetSymbolAddress((void**)&zhi, g_zhi);   cudaGetSymbolAddress((void**)&zlo, g_zlo);
    cudaGetSymbolAddress((void**)&ihi, g_ihi);   cudaGetSymbolAddress((void**)&ilo, g_ilo);
    cudaGetSymbolAddress((void**)&hhi, g_hhi);   cudaGetSymbolAddress((void**)&hlo, g_hlo);
    cudaGetSymbolAddress((void**)&w1hi, g_w1hi); cudaGetSymbolAddress((void**)&w1lo, g_w1lo);
    cudaGetSymbolAddress((void**)&w2hi, g_w2hi); cudaGetSymbolAddress((void**)&w2lo, g_w2lo);
    cudaGetSymbolAddress((void**)&wchi, g_wchi); cudaGetSymbolAddress((void**)&wclo, g_wclo);
    cudaGetSymbolAddress((void**)&bcat, g_bcat);
    cudaGetSymbolAddress((void**)&lv, g_lv);

    const int SMEM_BYTES = 3 * 36864 + 512;   // 111104
    cudaFuncSetAttribute((void*)gemm_mma<true, 1, 3>,  cudaFuncAttributeMaxDynamicSharedMemorySize, SMEM_BYTES);
    cudaFuncSetAttribute((void*)gemm_mma<false, 1, 3>, cudaFuncAttributeMaxDynamicSharedMemorySize, SMEM_BYTES);
    cudaFuncSetAttribute((void*)gemm_mma<false, 2, 2>, cudaFuncAttributeMaxDynamicSharedMemorySize, SMEM_BYTES);

    // converts
    split_act<<<(BATCH * HID / 4) / 256, 256>>>(z, zhi, zlo);
    split_w<<<dim3(HID / 32, HID / 32), 256>>>(W1, w1hi, w1lo, HID, HID, 1);
    split_w<<<dim3(HID / 32, HID / 32), 256>>>(W2, w2hi, w2lo, HID, HID, 1);
    split_w<<<dim3(NM  / 32, HID / 32), 256>>>(Wm, wchi, wclo, HID, NM, 0);
    split_w<<<dim3(NV  / 32, HID / 32), 256>>>(Wv, wchi + (size_t)NM * HID,
                                               wclo + (size_t)NM * HID, HID, NV, 0);
    concat_bias<<<(NCAT + 255) / 256, 256>>>(bm, bv, bcat);

    // GEMM chain (CTA 256x128)
    gemm_mma<true, 1, 3><<<dim3(HID / 128, BATCH / 256), 256, SMEM_BYTES>>>(
        zhi, zlo, w1hi, w1lo, b1, nullptr, nullptr, ihi, ilo);
    gemm_mma<false, 1, 3><<<dim3(HID / 128, BATCH / 256), 256, SMEM_BYTES>>>(
        ihi, ilo, w2hi, w2lo, b2, nullptr, nullptr, hhi, hlo);
    gemm_mma<false, 2, 2><<<dim3(NCAT / 128, BATCH / 256), 256, SMEM_BYTES>>>(
        hhi, hlo, wchi, wclo, bcat, means, lv, nullptr, nullptr);

    mvn_epilogue<<<(BATCH * FH) / 4, 256>>>(lv, prec, Dout, Tout);
}

// round 9
// speedup vs baseline: 1.4307x; 1.0705x over previous
#include <cuda_runtime.h>
#include <cuda_fp16.h>
#include <math.h>
#include <stdint.h>

#define BATCH 8192
#define HID   1024
#define FH    96
#define O_DIM 8
#define E_DIM 36
#define NM    768
#define NV    3456
#define NCAT  (NM + NV)     // 4224

// ---------------------------------------------------------------------------
// Device scratch (allocation-free per harness rules)
// ---------------------------------------------------------------------------
__device__ __half g_zhi[(size_t)BATCH * HID];
__device__ __half g_zlo[(size_t)BATCH * HID];
__device__ __half g_ihi[(size_t)BATCH * HID];
__device__ __half g_ilo[(size_t)BATCH * HID];
__device__ __half g_hhi[(size_t)BATCH * HID];
__device__ __half g_hlo[(size_t)BATCH * HID];
__device__ __half g_w1hi[(size_t)HID * HID];
__device__ __half g_w2hi[(size_t)HID * HID];
__device__ __half g_wchi[(size_t)NCAT * HID];   // [Wm|Wv]^T hi
__device__ float  g_bcat[NCAT];
__device__ float  g_lv[(size_t)BATCH * NV];

// ---------------------------------------------------------------------------
// helpers
// ---------------------------------------------------------------------------
__device__ __forceinline__ uint32_t smem_u32(const void* p) {
    uint32_t a;
    asm("{ .reg .u64 t; cvta.to.shared.u64 t, %1; cvt.u32.u64 %0, t; }" : "=r"(a) : "l"(p));
    return a;
}

__device__ __forceinline__ void cp16(uint32_t dst, const void* src) {
    asm volatile("cp.async.cg.shared.global [%0], [%1], 16;" :: "r"(dst), "l"(src));
}
#define CP_COMMIT() asm volatile("cp.async.commit_group;" ::: "memory")
#define CP_WAIT0()  asm volatile("cp.async.wait_group 0;"  ::: "memory")
#define CP_WAIT1()  asm volatile("cp.async.wait_group 1;"  ::: "memory")

__device__ __forceinline__ void ldsm4(uint32_t* r, uint32_t addr) {
    asm volatile("ldmatrix.sync.aligned.m8n8.x4.shared.b16 {%0,%1,%2,%3}, [%4];"
        : "=r"(r[0]), "=r"(r[1]), "=r"(r[2]), "=r"(r[3]) : "r"(addr));
}

__device__ __forceinline__ void mma16816(float* d, const uint32_t* a, const uint32_t* b)
{
    asm volatile(
        "mma.sync.aligned.m16n8k16.row.col.f32.f16.f16.f32 "
        "{%0,%1,%2,%3},{%4,%5,%6,%7},{%8,%9},{%0,%1,%2,%3};\n"
        : "+f"(d[0]), "+f"(d[1]), "+f"(d[2]), "+f"(d[3])
        : "r"(a[0]), "r"(a[1]), "r"(a[2]), "r"(a[3]), "r"(b[0]), "r"(b[1]));
}

__device__ __forceinline__ uint32_t hpack2(float a, float b) {
    __half2 t = __halves2half2(__float2half_rn(a), __float2half_rn(b));
    return *reinterpret_cast<uint32_t*>(&t);
}

// ---------------------------------------------------------------------------
// split_act: fp32 [n] -> hi fp16 [n], lo fp16 [n]
// ---------------------------------------------------------------------------
__global__ __launch_bounds__(256)
void split_act(const float* __restrict__ x,
               __half* __restrict__ hi, __half* __restrict__ lo)
{
    size_t idx = ((size_t)blockIdx.x * blockDim.x + threadIdx.x) * 4;
    float4 v = *(const float4*)(x + idx);
    __half h0 = __float2half_rn(v.x), h1 = __float2half_rn(v.y);
    __half h2 = __float2half_rn(v.z), h3 = __float2half_rn(v.w);
    uint2 hp, lp;
    { __half2 a = __halves2half2(h0, h1), b = __halves2half2(h2, h3);
      hp.x = *(uint32_t*)&a; hp.y = *(uint32_t*)&b; }
    lp.x = hpack2(v.x - __half2float(h0), v.y - __half2float(h1));
    lp.y = hpack2(v.z - __half2float(h2), v.w - __half2float(h3));
    *(uint2*)(hi + idx) = hp;
    *(uint2*)(lo + idx) = lp;
}

// ---------------------------------------------------------------------------
// split_w: W fp32 [K, N] -> Wt hi fp16 [N, K] (transposed, hi only)
// ---------------------------------------------------------------------------
__global__ __launch_bounds__(256)
void split_w(const float* __restrict__ W, __half* __restrict__ Whi, int K, int N)
{
    __shared__ float tile[32][33];
    const int k0 = blockIdx.y * 32, n0 = blockIdx.x * 32;
    const int tx = threadIdx.x & 31, ty = threadIdx.x >> 5;
#pragma unroll
    for (int r = ty; r < 32; r += 8)
        tile[r][tx] = W[(size_t)(k0 + r) * N + n0 + tx];
    __syncthreads();
#pragma unroll
    for (int i = threadIdx.x; i < 32 * 16; i += 256) {
        int nl = i >> 4, kp = i & 15;
        float a = tile[2 * kp][nl], b = tile[2 * kp + 1][nl];
        size_t base = (size_t)(n0 + nl) * K + k0 + 2 * kp;
        *(uint32_t*)(Whi + base) = hpack2(a, b);
    }
}

// concat biases into g_bcat
__global__ void concat_bias(const float* __restrict__ bm, const float* __restrict__ bv,
                            float* __restrict__ bcat)
{
    int i = blockIdx.x * blockDim.x + threadIdx.x;
    if (i < NCAT) bcat[i] = (i < NM) ? bm[i] : bv[i - NM];
}

// ---------------------------------------------------------------------------
// fp16 2-pass split GEMM: C[M,N] = act((A_hi + A_lo) @ B_hi^T + bias)
// CTA 256x128, BK=16, 8 warps (4M x 2N), warp tile 64x64.
// 3-stage cp.async pipeline, ldmatrix, independent MMA sweeps (no RAW pairs).
// OUTMODE 1: fp16 hi/lo out (Chi/Clo), N must be HID.
// OUTMODE 2: dual fp32 out: cols [0,NM) -> Cf0 (stride NM), [NM,NCAT) -> Cf1 (stride NV).
// ---------------------------------------------------------------------------
template <bool SILU, int OUTMODE>
__global__ __launch_bounds__(256, 1)
void gemm_mma(const __half* __restrict__ Ahi, const __half* __restrict__ Alo,
              const __half* __restrict__ Bthi,
              const float* __restrict__ bias,
              float* __restrict__ Cf0, float* __restrict__ Cf1,
              __half* __restrict__ Chi, __half* __restrict__ Clo)
{
    constexpr int K = HID;
    constexpr int NITER = K / 16;          // 64 k-steps
    constexpr int RS = 48;                 // 16 fp16 = 32B + 16B pad
    constexpr int SA_HI = 0;
    constexpr int SA_LO = 256 * RS;        // 12288
    constexpr int SB_HI = 2 * 256 * RS;    // 24576
    constexpr int STAGE = SB_HI + 128 * RS;// 30720
    constexpr int BIASOFF = 3 * STAGE;     // 92160

    extern __shared__ __align__(128) char smem[];
    const uint32_t sb = smem_u32(smem);
    float* sBias = (float*)(smem + BIASOFF);

    const int tid  = threadIdx.x;
    const int lane = tid & 31;
    const int wid  = tid >> 5;
    const int g = lane >> 2;               // 0..7
    const int t = lane & 3;                // 0..3
    const int m0 = (wid & 3) * 64;         // 4 warps along M
    const int n0 = (wid >> 2) * 64;        // 2 warps along N

    const int blockM = blockIdx.y * 256;
    const int blockN = blockIdx.x * 128;

    if (tid < 128) sBias[tid] = bias[blockN + tid];

    // ldmatrix per-lane address offsets (within a stage buffer)
    const uint32_t aoff = (uint32_t)(m0 + (lane & 15)) * RS + (uint32_t)(lane >> 4) * 16;
    const uint32_t boff = (uint32_t)(n0 + ((lane >> 4) << 3) + (lane & 7)) * RS
                        + (uint32_t)((lane >> 3) & 1) * 16;

    const __half* Ahi_b = Ahi + (size_t)blockM * K;
    const __half* Alo_b = Alo + (size_t)blockM * K;
    const __half* Bhi_b = Bthi + (size_t)blockN * K;

    auto load_stage = [&](int s) {
        const int k0 = s * 16;
        const uint32_t buf = sb + (s % 3) * STAGE;
#pragma unroll
        for (int j = 0; j < 2; j++) {
            const int idx = tid + 256 * j;
            const int row = idx >> 1, ch = idx & 1;
            const size_t goff = (size_t)row * K + k0 + ch * 8;
            const uint32_t soff = row * RS + ch * 16;
            cp16(buf + SA_HI + soff, Ahi_b + goff);
            cp16(buf + SA_LO + soff, Alo_b + goff);
        }
        {
            const int row = tid >> 1, ch = tid & 1;
            const size_t goff = (size_t)row * K + k0 + ch * 8;
            const uint32_t soff = row * RS + ch * 16;
            cp16(buf + SB_HI + soff, Bhi_b + goff);
        }
    };

    float acc[4][8][4];
#pragma unroll
    for (int mt = 0; mt < 4; mt++)
#pragma unroll
        for (int nt = 0; nt < 8; nt++)
#pragma unroll
            for (int c = 0; c < 4; c++) acc[mt][nt][c] = 0.f;

    load_stage(0); CP_COMMIT();
    load_stage(1); CP_COMMIT();

    for (int it = 0; it < NITER; ++it) {
        if (it == NITER - 1) { CP_WAIT0(); } else { CP_WAIT1(); }
        __syncthreads();
        if (it + 2 < NITER) { load_stage(it + 2); CP_COMMIT(); }

        const uint32_t buf = sb + (it % 3) * STAGE;
        const uint32_t aHi = buf + SA_HI + aoff;
        const uint32_t aLo = buf + SA_LO + aoff;
        const uint32_t bHi = buf + SB_HI + boff;

        uint32_t fAhi[4][4], fAlo[4][4], fBhi[8][2];
#pragma unroll
        for (int mt = 0; mt < 4; mt++) {
            ldsm4(fAhi[mt], aHi + mt * 16 * RS);
            ldsm4(fAlo[mt], aLo + mt * 16 * RS);
        }
#pragma unroll
        for (int nt = 0; nt < 8; nt += 2)
            ldsm4(&fBhi[nt][0], bHi + nt * 8 * RS);

        // two independent sweeps: each acc tile touched 32 MMAs apart
#pragma unroll
        for (int mt = 0; mt < 4; mt++)
#pragma unroll
            for (int nt = 0; nt < 8; nt++)
                mma16816(acc[mt][nt], fAhi[mt], fBhi[nt]);
#pragma unroll
        for (int mt = 0; mt < 4; mt++)
#pragma unroll
            for (int nt = 0; nt < 8; nt++)
                mma16816(acc[mt][nt], fAlo[mt], fBhi[nt]);
    }

    // output target for OUTMODE 2 (block never straddles NM boundary: 768 % 128 == 0)
    float* Cout = nullptr;
    int cstride = 0, cbase = 0;
    if (OUTMODE == 2) {
        if (blockN < NM) { Cout = Cf0; cstride = NM; cbase = blockN; }
        else             { Cout = Cf1; cstride = NV; cbase = blockN - NM; }
    }

    // epilogue
#pragma unroll
    for (int mt = 0; mt < 4; mt++) {
        const int row0 = blockM + m0 + mt * 16 + g;
#pragma unroll
        for (int nt = 0; nt < 8; nt++) {
            const int coll = n0 + nt * 8 + 2 * t;
            const float bv0 = sBias[coll], bv1 = sBias[coll + 1];
            float v00 = acc[mt][nt][0] + bv0, v01 = acc[mt][nt][1] + bv1;
            float v10 = acc[mt][nt][2] + bv0, v11 = acc[mt][nt][3] + bv1;
            if (SILU) {
                v00 = v00 / (1.f + expf(-v00));
                v01 = v01 / (1.f + expf(-v01));
                v10 = v10 / (1.f + expf(-v10));
                v11 = v11 / (1.f + expf(-v11));
            }
            if (OUTMODE == 2) {
                const int col = cbase + coll;
                float2 a = {v00, v01}, b = {v10, v11};
                *(float2*)(Cout + (size_t)row0 * cstride + col)       = a;
                *(float2*)(Cout + (size_t)(row0 + 8) * cstride + col) = b;
            } else {
                const int col = blockN + coll;
                __half h00 = __float2half_rn(v00), h01 = __float2half_rn(v01);
                __half h10 = __float2half_rn(v10), h11 = __float2half_rn(v11);
                size_t p0 = (size_t)row0 * HID + col;
                size_t p1 = (size_t)(row0 + 8) * HID + col;
                { __half2 x = __halves2half2(h00, h01);
                  *(uint32_t*)(Chi + p0) = *(uint32_t*)&x; }
                { __half2 x = __halves2half2(h10, h11);
                  *(uint32_t*)(Chi + p1) = *(uint32_t*)&x; }
                *(uint32_t*)(Clo + p0) = hpack2(v00 - __half2float(h00), v01 - __half2float(h01));
                *(uint32_t*)(Clo + p1) = hpack2(v10 - __half2float(h10), v11 - __half2float(h11));
            }
        }
    }
}

// ---------------------------------------------------------------------------
// MVN epilogue
// ---------------------------------------------------------------------------
__device__ __forceinline__ int triu_idx(int r, int c) {
    return r * (15 - r) / 2 + (c - r - 1);
}

__global__ __launch_bounds__(256)
void mvn_epilogue(const float* __restrict__ lv,
                  float* __restrict__ prec,
                  float* __restrict__ Dout,
                  float* __restrict__ Tout)
{
    constexpr int GP = 4;
    __shared__ float s_eta[GP][E_DIM];
    __shared__ float s_d[GP][O_DIM];
    __shared__ float s_dinv[GP][O_DIM];

    const int g = threadIdx.x >> 6;
    const int t = threadIdx.x & 63;
    const size_t bh = (size_t)blockIdx.x * GP + g;

    if (t < E_DIM) s_eta[g][t] = lv[bh * E_DIM + t];
    __syncthreads();
    if (t < O_DIM) {
        float d = expf(0.5f * s_eta[g][t]);
        s_d[g][t] = d;
        s_dinv[g][t] = 1.f / d;
    }
    __syncthreads();

    const int i = t >> 3, k = t & 7;
    const float* e = s_eta[g];
    const float* dinv = s_dinv[g];

    float tv = (i == k) ? 1.f : ((i < k) ? e[O_DIM + triu_idx(i, k)] : 0.f);
    float dv = (i == k) ? s_d[g][i] : 0.f;
    float s = 0.f;
#pragma unroll
    for (int j = 0; j < O_DIM; j++) {
        float tji = (j == i) ? 1.f : ((j < i) ? e[O_DIM + triu_idx(j, i)] : 0.f);
        float tjk = (j == k) ? 1.f : ((j < k) ? e[O_DIM + triu_idx(j, k)] : 0.f);
        s = fmaf(tji * tjk, dinv[j], s);
    }

    const size_t base = bh * (O_DIM * O_DIM) + t;
    prec[base] = s;
    Dout[base] = dv;
    Tout[base] = tv;
}

// ---------------------------------------------------------------------------
// Launch
// ---------------------------------------------------------------------------
extern "C" void kernel_launch(void* const* d_in, const int* in_sizes, int n_in,
                              void* d_out, int out_size)
{
    const float* z  = (const float*)d_in[0];
    const float* W1 = (const float*)d_in[1];
    const float* b1 = (const float*)d_in[2];
    const float* W2 = (const float*)d_in[3];
    const float* b2 = (const float*)d_in[4];
    const float* Wm = (const float*)d_in[5];
    const float* bm = (const float*)d_in[6];
    const float* Wv = (const float*)d_in[7];
    const float* bv = (const float*)d_in[8];

    float* out = (float*)d_out;
    const size_t n_means = (size_t)BATCH * FH * O_DIM;
    const size_t n_mat   = (size_t)BATCH * FH * O_DIM * O_DIM;
    float* means = out;
    float* prec  = out + n_means;
    float* Dout  = prec + n_mat;
    float* Tout  = Dout + n_mat;

    __half *zhi, *zlo, *ihi, *ilo, *hhi, *hlo;
    __half *w1hi, *w2hi, *wchi;
    float *lv, *bcat;
    cudaGetSymbolAddress((void**)&zhi, g_zhi);   cudaGetSymbolAddress((void**)&zlo, g_zlo);
    cudaGetSymbolAddress((void**)&ihi, g_ihi);   cudaGetSymbolAddress((void**)&ilo, g_ilo);
    cudaGetSymbolAddress((void**)&hhi, g_hhi);   cudaGetSymbolAddress((void**)&hlo, g_hlo);
    cudaGetSymbolAddress((void**)&w1hi, g_w1hi);
    cudaGetSymbolAddress((void**)&w2hi, g_w2hi);
    cudaGetSymbolAddress((void**)&wchi, g_wchi);
    cudaGetSymbolAddress((void**)&bcat, g_bcat);
    cudaGetSymbolAddress((void**)&lv, g_lv);

    const int SMEM_BYTES = 3 * 30720 + 512;   // 92672
    cudaFuncSetAttribute((void*)gemm_mma<true, 1>,  cudaFuncAttributeMaxDynamicSharedMemorySize, SMEM_BYTES);
    cudaFuncSetAttribute((void*)gemm_mma<false, 1>, cudaFuncAttributeMaxDynamicSharedMemorySize, SMEM_BYTES);
    cudaFuncSetAttribute((void*)gemm_mma<false, 2>, cudaFuncAttributeMaxDynamicSharedMemorySize, SMEM_BYTES);

    // converts (hi-only weights; activations keep hi+lo)
    split_act<<<(BATCH * HID / 4) / 256, 256>>>(z, zhi, zlo);
    split_w<<<dim3(HID / 32, HID / 32), 256>>>(W1, w1hi, HID, HID);
    split_w<<<dim3(HID / 32, HID / 32), 256>>>(W2, w2hi, HID, HID);
    split_w<<<dim3(NM  / 32, HID / 32), 256>>>(Wm, wchi, HID, NM);
    split_w<<<dim3(NV  / 32, HID / 32), 256>>>(Wv, wchi + (size_t)NM * HID, HID, NV);
    concat_bias<<<(NCAT + 255) / 256, 256>>>(bm, bv, bcat);

    // GEMM chain (CTA 256x128, 2-pass split everywhere)
    gemm_mma<true, 1><<<dim3(HID / 128, BATCH / 256), 256, SMEM_BYTES>>>(
        zhi, zlo, w1hi, b1, nullptr, nullptr, ihi, ilo);
    gemm_mma<false, 1><<<dim3(HID / 128, BATCH / 256), 256, SMEM_BYTES>>>(
        ihi, ilo, w2hi, b2, nullptr, nullptr, hhi, hlo);
    gemm_mma<false, 2><<<dim3(NCAT / 128, BATCH / 256), 256, SMEM_BYTES>>>(
        hhi, hlo, wchi, bcat, means, lv, nullptr, nullptr);

    mvn_epilogue<<<(BATCH * FH) / 4, 256>>>(lv, prec, Dout, Tout);
}

// round 10
// speedup vs baseline: 1.7510x; 1.2239x over previous
#include <cuda_runtime.h>
#include <cuda_fp16.h>
#include <math.h>
#include <stdint.h>

#define BATCH 8192
#define HID   1024
#define FH    96
#define O_DIM 8
#define E_DIM 36
#define NM    768
#define NV    3456
#define NCAT  (NM + NV)     // 4224

// ---------------------------------------------------------------------------
// Device scratch (allocation-free per harness rules)
// ---------------------------------------------------------------------------
__device__ __half g_zhi[(size_t)BATCH * HID];
__device__ __half g_zlo[(size_t)BATCH * HID];
__device__ __half g_ihi[(size_t)BATCH * HID];
__device__ __half g_ilo[(size_t)BATCH * HID];
__device__ __half g_hhi[(size_t)BATCH * HID];
__device__ __half g_w1hi[(size_t)HID * HID];
__device__ __half g_w2hi[(size_t)HID * HID];
__device__ __half g_wchi[(size_t)NCAT * HID];   // [Wm|Wv]^T hi
__device__ float  g_bcat[NCAT];
__device__ float  g_lv[(size_t)BATCH * NV];

// ---------------------------------------------------------------------------
// helpers
// ---------------------------------------------------------------------------
__device__ __forceinline__ uint32_t smem_u32(const void* p) {
    uint32_t a;
    asm("{ .reg .u64 t; cvta.to.shared.u64 t, %1; cvt.u32.u64 %0, t; }" : "=r"(a) : "l"(p));
    return a;
}

__device__ __forceinline__ void cp16(uint32_t dst, const void* src) {
    asm volatile("cp.async.cg.shared.global [%0], [%1], 16;" :: "r"(dst), "l"(src));
}
#define CP_COMMIT() asm volatile("cp.async.commit_group;" ::: "memory")
#define CP_WAIT0()  asm volatile("cp.async.wait_group 0;"  ::: "memory")
#define CP_WAIT1()  asm volatile("cp.async.wait_group 1;"  ::: "memory")

__device__ __forceinline__ void ldsm4(uint32_t* r, uint32_t addr) {
    asm volatile("ldmatrix.sync.aligned.m8n8.x4.shared.b16 {%0,%1,%2,%3}, [%4];"
        : "=r"(r[0]), "=r"(r[1]), "=r"(r[2]), "=r"(r[3]) : "r"(addr));
}

__device__ __forceinline__ void mma16816(float* d, const uint32_t* a, const uint32_t* b)
{
    asm volatile(
        "mma.sync.aligned.m16n8k16.row.col.f32.f16.f16.f32 "
        "{%0,%1,%2,%3},{%4,%5,%6,%7},{%8,%9},{%0,%1,%2,%3};\n"
        : "+f"(d[0]), "+f"(d[1]), "+f"(d[2]), "+f"(d[3])
        : "r"(a[0]), "r"(a[1]), "r"(a[2]), "r"(a[3]), "r"(b[0]), "r"(b[1]));
}

__device__ __forceinline__ uint32_t hpack2(float a, float b) {
    __half2 t = __halves2half2(__float2half_rn(a), __float2half_rn(b));
    return *reinterpret_cast<uint32_t*>(&t);
}

// ---------------------------------------------------------------------------
// split_act: fp32 [n] -> hi fp16 [n], lo fp16 [n]
// ---------------------------------------------------------------------------
__global__ __launch_bounds__(256)
void split_act(const float* __restrict__ x,
               __half* __restrict__ hi, __half* __restrict__ lo)
{
    size_t idx = ((size_t)blockIdx.x * blockDim.x + threadIdx.x) * 4;
    float4 v = *(const float4*)(x + idx);
    __half h0 = __float2half_rn(v.x), h1 = __float2half_rn(v.y);
    __half h2 = __float2half_rn(v.z), h3 = __float2half_rn(v.w);
    uint2 hp, lp;
    { __half2 a = __halves2half2(h0, h1), b = __halves2half2(h2, h3);
      hp.x = *(uint32_t*)&a; hp.y = *(uint32_t*)&b; }
    lp.x = hpack2(v.x - __half2float(h0), v.y - __half2float(h1));
    lp.y = hpack2(v.z - __half2float(h2), v.w - __half2float(h3));
    *(uint2*)(hi + idx) = hp;
    *(uint2*)(lo + idx) = lp;
}

// ---------------------------------------------------------------------------
// split_w: W fp32 [K, N] -> Wt hi fp16 [N, K] (transposed, hi only)
// ---------------------------------------------------------------------------
__global__ __launch_bounds__(256)
void split_w(const float* __restrict__ W, __half* __restrict__ Whi, int K, int N)
{
    __shared__ float tile[32][33];
    const int k0 = blockIdx.y * 32, n0 = blockIdx.x * 32;
    const int tx = threadIdx.x & 31, ty = threadIdx.x >> 5;
#pragma unroll
    for (int r = ty; r < 32; r += 8)
        tile[r][tx] = W[(size_t)(k0 + r) * N + n0 + tx];
    __syncthreads();
#pragma unroll
    for (int i = threadIdx.x; i < 32 * 16; i += 256) {
        int nl = i >> 4, kp = i & 15;
        float a = tile[2 * kp][nl], b = tile[2 * kp + 1][nl];
        size_t base = (size_t)(n0 + nl) * K + k0 + 2 * kp;
        *(uint32_t*)(Whi + base) = hpack2(a, b);
    }
}

// concat biases into g_bcat
__global__ void concat_bias(const float* __restrict__ bm, const float* __restrict__ bv,
                            float* __restrict__ bcat)
{
    int i = blockIdx.x * blockDim.x + threadIdx.x;
    if (i < NCAT) bcat[i] = (i < NM) ? bm[i] : bv[i - NM];
}

// ---------------------------------------------------------------------------
// fp16 split GEMM: C[M,N] = act(A @ B_hi^T + bias), A = A_hi (+ A_lo if PASSES==2)
// CTA 256x128, BK=16, 8 warps (4M x 2N), warp tile 64x64.
// 3-stage cp.async pipeline, ldmatrix, independent MMA sweeps (no RAW pairs).
// OUTMODE 1: fp16 hi+lo out (Chi/Clo), N must be HID.
// OUTMODE 3: fp16 hi-only out (Chi),   N must be HID.
// OUTMODE 2: dual fp32 out: cols [0,NM) -> Cf0 (stride NM), [NM,NCAT) -> Cf1 (stride NV).
// ---------------------------------------------------------------------------
template <bool SILU, int OUTMODE, int PASSES>
__global__ __launch_bounds__(256, 1)
void gemm_mma(const __half* __restrict__ Ahi, const __half* __restrict__ Alo,
              const __half* __restrict__ Bthi,
              const float* __restrict__ bias,
              float* __restrict__ Cf0, float* __restrict__ Cf1,
              __half* __restrict__ Chi, __half* __restrict__ Clo)
{
    constexpr int K = HID;
    constexpr int NITER = K / 16;          // 64 k-steps
    constexpr int RS = 48;                 // 16 fp16 = 32B + 16B pad
    constexpr int SA_HI = 0;
    constexpr int SA_LO = 256 * RS;        // 12288
    constexpr int SB_HI = (PASSES == 2) ? (2 * 256 * RS) : (256 * RS);
    constexpr int STAGE = SB_HI + 128 * RS;
    constexpr int BIASOFF = 3 * STAGE;

    extern __shared__ __align__(128) char smem[];
    const uint32_t sb = smem_u32(smem);
    float* sBias = (float*)(smem + BIASOFF);

    const int tid  = threadIdx.x;
    const int lane = tid & 31;
    const int wid  = tid >> 5;
    const int g = lane >> 2;               // 0..7
    const int t = lane & 3;                // 0..3
    const int m0 = (wid & 3) * 64;         // 4 warps along M
    const int n0 = (wid >> 2) * 64;        // 2 warps along N

    const int blockM = blockIdx.y * 256;
    const int blockN = blockIdx.x * 128;

    if (tid < 128) sBias[tid] = bias[blockN + tid];

    // ldmatrix per-lane address offsets (within a stage buffer)
    const uint32_t aoff = (uint32_t)(m0 + (lane & 15)) * RS + (uint32_t)(lane >> 4) * 16;
    const uint32_t boff = (uint32_t)(n0 + ((lane >> 4) << 3) + (lane & 7)) * RS
                        + (uint32_t)((lane >> 3) & 1) * 16;

    const __half* Ahi_b = Ahi + (size_t)blockM * K;
    const __half* Alo_b = (PASSES == 2) ? (Alo + (size_t)blockM * K) : nullptr;
    const __half* Bhi_b = Bthi + (size_t)blockN * K;

    auto load_stage = [&](int s) {
        const int k0 = s * 16;
        const uint32_t buf = sb + (s % 3) * STAGE;
#pragma unroll
        for (int j = 0; j < 2; j++) {
            const int idx = tid + 256 * j;
            const int row = idx >> 1, ch = idx & 1;
            const size_t goff = (size_t)row * K + k0 + ch * 8;
            const uint32_t soff = row * RS + ch * 16;
            cp16(buf + SA_HI + soff, Ahi_b + goff);
            if (PASSES == 2)
                cp16(buf + SA_LO + soff, Alo_b + goff);
        }
        {
            const int row = tid >> 1, ch = tid & 1;
            const size_t goff = (size_t)row * K + k0 + ch * 8;
            const uint32_t soff = row * RS + ch * 16;
            cp16(buf + SB_HI + soff, Bhi_b + goff);
        }
    };

    float acc[4][8][4];
#pragma unroll
    for (int mt = 0; mt < 4; mt++)
#pragma unroll
        for (int nt = 0; nt < 8; nt++)
#pragma unroll
            for (int c = 0; c < 4; c++) acc[mt][nt][c] = 0.f;

    load_stage(0); CP_COMMIT();
    load_stage(1); CP_COMMIT();

    for (int it = 0; it < NITER; ++it) {
        if (it == NITER - 1) { CP_WAIT0(); } else { CP_WAIT1(); }
        __syncthreads();
        if (it + 2 < NITER) { load_stage(it + 2); CP_COMMIT(); }

        const uint32_t buf = sb + (it % 3) * STAGE;
        const uint32_t aHi = buf + SA_HI + aoff;
        const uint32_t aLo = buf + SA_LO + aoff;
        const uint32_t bHi = buf + SB_HI + boff;

        uint32_t fAhi[4][4], fAlo[4][4], fBhi[8][2];
#pragma unroll
        for (int mt = 0; mt < 4; mt++) {
            ldsm4(fAhi[mt], aHi + mt * 16 * RS);
            if (PASSES == 2)
                ldsm4(fAlo[mt], aLo + mt * 16 * RS);
        }
#pragma unroll
        for (int nt = 0; nt < 8; nt += 2)
            ldsm4(&fBhi[nt][0], bHi + nt * 8 * RS);

        // independent sweeps: each acc tile touched 32 MMAs apart
#pragma unroll
        for (int mt = 0; mt < 4; mt++)
#pragma unroll
            for (int nt = 0; nt < 8; nt++)
                mma16816(acc[mt][nt], fAhi[mt], fBhi[nt]);
        if (PASSES == 2) {
#pragma unroll
            for (int mt = 0; mt < 4; mt++)
#pragma unroll
                for (int nt = 0; nt < 8; nt++)
                    mma16816(acc[mt][nt], fAlo[mt], fBhi[nt]);
        }
    }

    // output target for OUTMODE 2 (block never straddles NM boundary: 768 % 128 == 0)
    float* Cout = nullptr;
    int cstride = 0, cbase = 0;
    if (OUTMODE == 2) {
        if (blockN < NM) { Cout = Cf0; cstride = NM; cbase = blockN; }
        else             { Cout = Cf1; cstride = NV; cbase = blockN - NM; }
    }

    // epilogue
#pragma unroll
    for (int mt = 0; mt < 4; mt++) {
        const int row0 = blockM + m0 + mt * 16 + g;
#pragma unroll
        for (int nt = 0; nt < 8; nt++) {
            const int coll = n0 + nt * 8 + 2 * t;
            const float bv0 = sBias[coll], bv1 = sBias[coll + 1];
            float v00 = acc[mt][nt][0] + bv0, v01 = acc[mt][nt][1] + bv1;
            float v10 = acc[mt][nt][2] + bv0, v11 = acc[mt][nt][3] + bv1;
            if (SILU) {
                v00 = v00 / (1.f + expf(-v00));
                v01 = v01 / (1.f + expf(-v01));
                v10 = v10 / (1.f + expf(-v10));
                v11 = v11 / (1.f + expf(-v11));
            }
            if (OUTMODE == 2) {
                const int col = cbase + coll;
                float2 a = {v00, v01}, b = {v10, v11};
                *(float2*)(Cout + (size_t)row0 * cstride + col)       = a;
                *(float2*)(Cout + (size_t)(row0 + 8) * cstride + col) = b;
            } else {
                const int col = blockN + coll;
                __half h00 = __float2half_rn(v00), h01 = __float2half_rn(v01);
                __half h10 = __float2half_rn(v10), h11 = __float2half_rn(v11);
                size_t p0 = (size_t)row0 * HID + col;
                size_t p1 = (size_t)(row0 + 8) * HID + col;
                { __half2 x = __halves2half2(h00, h01);
                  *(uint32_t*)(Chi + p0) = *(uint32_t*)&x; }
                { __half2 x = __halves2half2(h10, h11);
                  *(uint32_t*)(Chi + p1) = *(uint32_t*)&x; }
                if (OUTMODE == 1) {
                    *(uint32_t*)(Clo + p0) = hpack2(v00 - __half2float(h00), v01 - __half2float(h01));
                    *(uint32_t*)(Clo + p1) = hpack2(v10 - __half2float(h10), v11 - __half2float(h11));
                }
            }
        }
    }
}

// ---------------------------------------------------------------------------
// MVN epilogue
// ---------------------------------------------------------------------------
__device__ __forceinline__ int triu_idx(int r, int c) {
    return r * (15 - r) / 2 + (c - r - 1);
}

__global__ __launch_bounds__(256)
void mvn_epilogue(const float* __restrict__ lv,
                  float* __restrict__ prec,
                  float* __restrict__ Dout,
                  float* __restrict__ Tout)
{
    constexpr int GP = 4;
    __shared__ float s_eta[GP][E_DIM];
    __shared__ float s_d[GP][O_DIM];
    __shared__ float s_dinv[GP][O_DIM];

    const int g = threadIdx.x >> 6;
    const int t = threadIdx.x & 63;
    const size_t bh = (size_t)blockIdx.x * GP + g;

    if (t < E_DIM) s_eta[g][t] = lv[bh * E_DIM + t];
    __syncthreads();
    if (t < O_DIM) {
        float d = expf(0.5f * s_eta[g][t]);
        s_d[g][t] = d;
        s_dinv[g][t] = 1.f / d;
    }
    __syncthreads();

    const int i = t >> 3, k = t & 7;
    const float* e = s_eta[g];
    const float* dinv = s_dinv[g];

    float tv = (i == k) ? 1.f : ((i < k) ? e[O_DIM + triu_idx(i, k)] : 0.f);
    float dv = (i == k) ? s_d[g][i] : 0.f;
    float s = 0.f;
#pragma unroll
    for (int j = 0; j < O_DIM; j++) {
        float tji = (j == i) ? 1.f : ((j < i) ? e[O_DIM + triu_idx(j, i)] : 0.f);
        float tjk = (j == k) ? 1.f : ((j < k) ? e[O_DIM + triu_idx(j, k)] : 0.f);
        s = fmaf(tji * tjk, dinv[j], s);
    }

    const size_t base = bh * (O_DIM * O_DIM) + t;
    prec[base] = s;
    Dout[base] = dv;
    Tout[base] = tv;
}

// ---------------------------------------------------------------------------
// Launch
// ---------------------------------------------------------------------------
extern "C" void kernel_launch(void* const* d_in, const int* in_sizes, int n_in,
                              void* d_out, int out_size)
{
    const float* z  = (const float*)d_in[0];
    const float* W1 = (const float*)d_in[1];
    const float* b1 = (const float*)d_in[2];
    const float* W2 = (const float*)d_in[3];
    const float* b2 = (const float*)d_in[4];
    const float* Wm = (const float*)d_in[5];
    const float* bm = (const float*)d_in[6];
    const float* Wv = (const float*)d_in[7];
    const float* bv = (const float*)d_in[8];

    float* out = (float*)d_out;
    const size_t n_means = (size_t)BATCH * FH * O_DIM;
    const size_t n_mat   = (size_t)BATCH * FH * O_DIM * O_DIM;
    float* means = out;
    float* prec  = out + n_means;
    float* Dout  = prec + n_mat;
    float* Tout  = Dout + n_mat;

    __half *zhi, *zlo, *ihi, *ilo, *hhi;
    __half *w1hi, *w2hi, *wchi;
    float *lv, *bcat;
    cudaGetSymbolAddress((void**)&zhi, g_zhi);   cudaGetSymbolAddress((void**)&zlo, g_zlo);
    cudaGetSymbolAddress((void**)&ihi, g_ihi);   cudaGetSymbolAddress((void**)&ilo, g_ilo);
    cudaGetSymbolAddress((void**)&hhi, g_hhi);
    cudaGetSymbolAddress((void**)&w1hi, g_w1hi);
    cudaGetSymbolAddress((void**)&w2hi, g_w2hi);
    cudaGetSymbolAddress((void**)&wchi, g_wchi);
    cudaGetSymbolAddress((void**)&bcat, g_bcat);
    cudaGetSymbolAddress((void**)&lv, g_lv);

    const int SMEM2 = 3 * 30720 + 512;   // 92672 (PASSES=2 stage = 30720)
    const int SMEM1 = 3 * 18432 + 512;   // 55808 (PASSES=1 stage = 18432)
    cudaFuncSetAttribute((void*)gemm_mma<true, 1, 2>,  cudaFuncAttributeMaxDynamicSharedMemorySize, SMEM2);
    cudaFuncSetAttribute((void*)gemm_mma<false, 3, 2>, cudaFuncAttributeMaxDynamicSharedMemorySize, SMEM2);
    cudaFuncSetAttribute((void*)gemm_mma<false, 2, 1>, cudaFuncAttributeMaxDynamicSharedMemorySize, SMEM1);

    // converts (hi-only weights; z keeps hi+lo)
    split_act<<<(BATCH * HID / 4) / 256, 256>>>(z, zhi, zlo);
    split_w<<<dim3(HID / 32, HID / 32), 256>>>(W1, w1hi, HID, HID);
    split_w<<<dim3(HID / 32, HID / 32), 256>>>(W2, w2hi, HID, HID);
    split_w<<<dim3(NM  / 32, HID / 32), 256>>>(Wm, wchi, HID, NM);
    split_w<<<dim3(NV  / 32, HID / 32), 256>>>(Wv, wchi + (size_t)NM * HID, HID, NV);
    concat_bias<<<(NCAT + 255) / 256, 256>>>(bm, bv, bcat);

    // GEMM chain (CTA 256x128)
    gemm_mma<true, 1, 2><<<dim3(HID / 128, BATCH / 256), 256, SMEM2>>>(
        zhi, zlo, w1hi, b1, nullptr, nullptr, ihi, ilo);
    gemm_mma<false, 3, 2><<<dim3(HID / 128, BATCH / 256), 256, SMEM2>>>(
        ihi, ilo, w2hi, b2, nullptr, nullptr, hhi, nullptr);
    gemm_mma<false, 2, 1><<<dim3(NCAT / 128, BATCH / 256), 256, SMEM1>>>(
        hhi, nullptr, wchi, bcat, means, lv, nullptr, nullptr);

    mvn_epilogue<<<(BATCH * FH) / 4, 256>>>(lv, prec, Dout, Tout);
}

// round 11
// speedup vs baseline: 1.9152x; 1.0937x over previous
#include <cuda_runtime.h>
#include <cuda_fp16.h>
#include <math.h>
#include <stdint.h>

#define BATCH 8192
#define HID   1024
#define FH    96
#define O_DIM 8
#define E_DIM 36
#define NM    768
#define NV    3456
#define NCAT  (NM + NV)     // 4224

// ---------------------------------------------------------------------------
// Device scratch (allocation-free per harness rules)
// ---------------------------------------------------------------------------
__device__ __half g_zhi[(size_t)BATCH * HID];
__device__ __half g_zlo[(size_t)BATCH * HID];
__device__ __half g_ihi[(size_t)BATCH * HID];
__device__ __half g_ilo[(size_t)BATCH * HID];
__device__ __half g_hhi[(size_t)BATCH * HID];
__device__ __half g_w1hi[(size_t)HID * HID];
__device__ __half g_w2hi[(size_t)HID * HID];
__device__ __half g_wchi[(size_t)NCAT * HID];   // [Wm|Wv]^T hi
__device__ float  g_bcat[NCAT];
__device__ float  g_lv[(size_t)BATCH * NV];

// ---------------------------------------------------------------------------
// helpers
// ---------------------------------------------------------------------------
__device__ __forceinline__ uint32_t smem_u32(const void* p) {
    uint32_t a;
    asm("{ .reg .u64 t; cvta.to.shared.u64 t, %1; cvt.u32.u64 %0, t; }" : "=r"(a) : "l"(p));
    return a;
}

__device__ __forceinline__ void cp16(uint32_t dst, const void* src) {
    asm volatile("cp.async.cg.shared.global [%0], [%1], 16;" :: "r"(dst), "l"(src));
}
#define CP_COMMIT() asm volatile("cp.async.commit_group;" ::: "memory")
#define CP_WAIT0()  asm volatile("cp.async.wait_group 0;"  ::: "memory")
#define CP_WAIT1()  asm volatile("cp.async.wait_group 1;"  ::: "memory")

__device__ __forceinline__ void ldsm4(uint32_t* r, uint32_t addr) {
    asm volatile("ldmatrix.sync.aligned.m8n8.x4.shared.b16 {%0,%1,%2,%3}, [%4];"
        : "=r"(r[0]), "=r"(r[1]), "=r"(r[2]), "=r"(r[3]) : "r"(addr));
}

__device__ __forceinline__ void mma16816(float* d, const uint32_t* a, const uint32_t* b)
{
    asm volatile(
        "mma.sync.aligned.m16n8k16.row.col.f32.f16.f16.f32 "
        "{%0,%1,%2,%3},{%4,%5,%6,%7},{%8,%9},{%0,%1,%2,%3};\n"
        : "+f"(d[0]), "+f"(d[1]), "+f"(d[2]), "+f"(d[3])
        : "r"(a[0]), "r"(a[1]), "r"(a[2]), "r"(a[3]), "r"(b[0]), "r"(b[1]));
}

__device__ __forceinline__ uint32_t hpack2(float a, float b) {
    __half2 t = __halves2half2(__float2half_rn(a), __float2half_rn(b));
    return *reinterpret_cast<uint32_t*>(&t);
}

// ---------------------------------------------------------------------------
// split_act: fp32 [n] -> hi fp16 [n], lo fp16 [n]
// ---------------------------------------------------------------------------
__global__ __launch_bounds__(256)
void split_act(const float* __restrict__ x,
               __half* __restrict__ hi, __half* __restrict__ lo)
{
    size_t idx = ((size_t)blockIdx.x * blockDim.x + threadIdx.x) * 4;
    float4 v = *(const float4*)(x + idx);
    __half h0 = __float2half_rn(v.x), h1 = __float2half_rn(v.y);
    __half h2 = __float2half_rn(v.z), h3 = __float2half_rn(v.w);
    uint2 hp, lp;
    { __half2 a = __halves2half2(h0, h1), b = __halves2half2(h2, h3);
      hp.x = *(uint32_t*)&a; hp.y = *(uint32_t*)&b; }
    lp.x = hpack2(v.x - __half2float(h0), v.y - __half2float(h1));
    lp.y = hpack2(v.z - __half2float(h2), v.w - __half2float(h3));
    *(uint2*)(hi + idx) = hp;
    *(uint2*)(lo + idx) = lp;
}

// ---------------------------------------------------------------------------
// split_w: W fp32 [K, N] -> Wt hi fp16 [N, K] (transposed, hi only)
// ---------------------------------------------------------------------------
__global__ __launch_bounds__(256)
void split_w(const float* __restrict__ W, __half* __restrict__ Whi, int K, int N)
{
    __shared__ float tile[32][33];
    const int k0 = blockIdx.y * 32, n0 = blockIdx.x * 32;
    const int tx = threadIdx.x & 31, ty = threadIdx.x >> 5;
#pragma unroll
    for (int r = ty; r < 32; r += 8)
        tile[r][tx] = W[(size_t)(k0 + r) * N + n0 + tx];
    __syncthreads();
#pragma unroll
    for (int i = threadIdx.x; i < 32 * 16; i += 256) {
        int nl = i >> 4, kp = i & 15;
        float a = tile[2 * kp][nl], b = tile[2 * kp + 1][nl];
        size_t base = (size_t)(n0 + nl) * K + k0 + 2 * kp;
        *(uint32_t*)(Whi + base) = hpack2(a, b);
    }
}

// concat biases into g_bcat
__global__ void concat_bias(const float* __restrict__ bm, const float* __restrict__ bv,
                            float* __restrict__ bcat)
{
    int i = blockIdx.x * blockDim.x + threadIdx.x;
    if (i < NCAT) bcat[i] = (i < NM) ? bm[i] : bv[i - NM];
}

// ---------------------------------------------------------------------------
// fp16 split GEMM: C[M,N] = act(A @ B_hi^T + bias), A = A_hi (+ A_lo if PASSES==2)
// CTAM=256: CTA 256x128, 8 warps 4Mx2N, warp 64x64 (1 CTA/SM).
// CTAM=128: CTA 128x128, 8 warps 2Mx4N, warp 64x32 (2 CTAs/SM, reg-capped).
// 3-stage cp.async pipeline, ldmatrix, independent MMA sweeps.
// OUTMODE 1: fp16 hi+lo out (Chi/Clo). OUTMODE 3: fp16 hi-only out.
// OUTMODE 2: dual fp32: cols [0,NM) -> Cf0 (stride NM), rest -> Cf1 (stride NV).
// ---------------------------------------------------------------------------
template <bool SILU, int OUTMODE, int PASSES, int CTAM, int MINB>
__global__ __launch_bounds__(256, MINB)
void gemm_mma(const __half* __restrict__ Ahi, const __half* __restrict__ Alo,
              const __half* __restrict__ Bthi,
              const float* __restrict__ bias,
              float* __restrict__ Cf0, float* __restrict__ Cf1,
              __half* __restrict__ Chi, __half* __restrict__ Clo)
{
    constexpr int K = HID;
    constexpr int NITER = K / 16;          // 64 k-steps
    constexpr int RS = 48;                 // 16 fp16 = 32B + 16B pad
    constexpr int NT = (CTAM == 256) ? 8 : 4;   // n8 tiles per warp
    constexpr int SA_HI = 0;
    constexpr int SA_LO = CTAM * RS;
    constexpr int SB_HI = (PASSES == 2) ? (2 * CTAM * RS) : (CTAM * RS);
    constexpr int STAGE = SB_HI + 128 * RS;
    constexpr int BIASOFF = 3 * STAGE;

    extern __shared__ __align__(128) char smem[];
    const uint32_t sb = smem_u32(smem);
    float* sBias = (float*)(smem + BIASOFF);

    const int tid  = threadIdx.x;
    const int lane = tid & 31;
    const int wid  = tid >> 5;
    const int g = lane >> 2;               // 0..7
    const int t = lane & 3;                // 0..3
    const int m0 = (CTAM == 256) ? (wid & 3) * 64 : (wid & 1) * 64;
    const int n0 = (CTAM == 256) ? (wid >> 2) * 64 : (wid >> 1) * 32;

    const int blockM = blockIdx.y * CTAM;
    const int blockN = blockIdx.x * 128;

    if (tid < 128) sBias[tid] = bias[blockN + tid];

    // ldmatrix per-lane address offsets (within a stage buffer)
    const uint32_t aoff = (uint32_t)(m0 + (lane & 15)) * RS + (uint32_t)(lane >> 4) * 16;
    const uint32_t boff = (uint32_t)(n0 + ((lane >> 4) << 3) + (lane & 7)) * RS
                        + (uint32_t)((lane >> 3) & 1) * 16;

    const __half* Ahi_b = Ahi + (size_t)blockM * K;
    const __half* Alo_b = (PASSES == 2) ? (Alo + (size_t)blockM * K) : nullptr;
    const __half* Bhi_b = Bthi + (size_t)blockN * K;

    auto load_stage = [&](int s) {
        const int k0 = s * 16;
        const uint32_t buf = sb + (s % 3) * STAGE;
#pragma unroll
        for (int j = 0; j < CTAM / 128; j++) {
            const int idx = tid + 256 * j;
            const int row = idx >> 1, ch = idx & 1;
            const size_t goff = (size_t)row * K + k0 + ch * 8;
            const uint32_t soff = row * RS + ch * 16;
            cp16(buf + SA_HI + soff, Ahi_b + goff);
            if (PASSES == 2)
                cp16(buf + SA_LO + soff, Alo_b + goff);
        }
        {
            const int row = tid >> 1, ch = tid & 1;
            const size_t goff = (size_t)row * K + k0 + ch * 8;
            const uint32_t soff = row * RS + ch * 16;
            cp16(buf + SB_HI + soff, Bhi_b + goff);
        }
    };

    float acc[4][NT][4];
#pragma unroll
    for (int mt = 0; mt < 4; mt++)
#pragma unroll
        for (int nt = 0; nt < NT; nt++)
#pragma unroll
            for (int c = 0; c < 4; c++) acc[mt][nt][c] = 0.f;

    load_stage(0); CP_COMMIT();
    load_stage(1); CP_COMMIT();

    for (int it = 0; it < NITER; ++it) {
        if (it == NITER - 1) { CP_WAIT0(); } else { CP_WAIT1(); }
        __syncthreads();
        if (it + 2 < NITER) { load_stage(it + 2); CP_COMMIT(); }

        const uint32_t buf = sb + (it % 3) * STAGE;
        const uint32_t aHi = buf + SA_HI + aoff;
        const uint32_t aLo = buf + SA_LO + aoff;
        const uint32_t bHi = buf + SB_HI + boff;

        uint32_t fAhi[4][4], fAlo[4][4], fBhi[NT][2];
#pragma unroll
        for (int mt = 0; mt < 4; mt++) {
            ldsm4(fAhi[mt], aHi + mt * 16 * RS);
            if (PASSES == 2)
                ldsm4(fAlo[mt], aLo + mt * 16 * RS);
        }
#pragma unroll
        for (int nt = 0; nt < NT; nt += 2)
            ldsm4(&fBhi[nt][0], bHi + nt * 8 * RS);

        // independent sweeps: each acc tile touched many MMAs apart
#pragma unroll
        for (int mt = 0; mt < 4; mt++)
#pragma unroll
            for (int nt = 0; nt < NT; nt++)
                mma16816(acc[mt][nt], fAhi[mt], fBhi[nt]);
        if (PASSES == 2) {
#pragma unroll
            for (int mt = 0; mt < 4; mt++)
#pragma unroll
                for (int nt = 0; nt < NT; nt++)
                    mma16816(acc[mt][nt], fAlo[mt], fBhi[nt]);
        }
    }

    // output target for OUTMODE 2 (block never straddles NM boundary: 768 % 128 == 0)
    float* Cout = nullptr;
    int cstride = 0, cbase = 0;
    if (OUTMODE == 2) {
        if (blockN < NM) { Cout = Cf0; cstride = NM; cbase = blockN; }
        else             { Cout = Cf1; cstride = NV; cbase = blockN - NM; }
    }

    // epilogue
#pragma unroll
    for (int mt = 0; mt < 4; mt++) {
        const int row0 = blockM + m0 + mt * 16 + g;
#pragma unroll
        for (int nt = 0; nt < NT; nt++) {
            const int coll = n0 + nt * 8 + 2 * t;
            const float bv0 = sBias[coll], bv1 = sBias[coll + 1];
            float v00 = acc[mt][nt][0] + bv0, v01 = acc[mt][nt][1] + bv1;
            float v10 = acc[mt][nt][2] + bv0, v11 = acc[mt][nt][3] + bv1;
            if (SILU) {
                v00 = v00 / (1.f + expf(-v00));
                v01 = v01 / (1.f + expf(-v01));
                v10 = v10 / (1.f + expf(-v10));
                v11 = v11 / (1.f + expf(-v11));
            }
            if (OUTMODE == 2) {
                const int col = cbase + coll;
                float2 a = {v00, v01}, b = {v10, v11};
                *(float2*)(Cout + (size_t)row0 * cstride + col)       = a;
                *(float2*)(Cout + (size_t)(row0 + 8) * cstride + col) = b;
            } else {
                const int col = blockN + coll;
                __half h00 = __float2half_rn(v00), h01 = __float2half_rn(v01);
                __half h10 = __float2half_rn(v10), h11 = __float2half_rn(v11);
                size_t p0 = (size_t)row0 * HID + col;
                size_t p1 = (size_t)(row0 + 8) * HID + col;
                { __half2 x = __halves2half2(h00, h01);
                  *(uint32_t*)(Chi + p0) = *(uint32_t*)&x; }
                { __half2 x = __halves2half2(h10, h11);
                  *(uint32_t*)(Chi + p1) = *(uint32_t*)&x; }
                if (OUTMODE == 1) {
                    *(uint32_t*)(Clo + p0) = hpack2(v00 - __half2float(h00), v01 - __half2float(h01));
                    *(uint32_t*)(Clo + p1) = hpack2(v10 - __half2float(h10), v11 - __half2float(h11));
                }
            }
        }
    }
}

// ---------------------------------------------------------------------------
// MVN epilogue
// ---------------------------------------------------------------------------
__device__ __forceinline__ int triu_idx(int r, int c) {
    return r * (15 - r) / 2 + (c - r - 1);
}

__global__ __launch_bounds__(256)
void mvn_epilogue(const float* __restrict__ lv,
                  float* __restrict__ prec,
                  float* __restrict__ Dout,
                  float* __restrict__ Tout)
{
    constexpr int GP = 4;
    __shared__ float s_eta[GP][E_DIM];
    __shared__ float s_d[GP][O_DIM];
    __shared__ float s_dinv[GP][O_DIM];

    const int g = threadIdx.x >> 6;
    const int t = threadIdx.x & 63;
    const size_t bh = (size_t)blockIdx.x * GP + g;

    if (t < E_DIM) s_eta[g][t] = lv[bh * E_DIM + t];
    __syncthreads();
    if (t < O_DIM) {
        float d = expf(0.5f * s_eta[g][t]);
        s_d[g][t] = d;
        s_dinv[g][t] = 1.f / d;
    }
    __syncthreads();

    const int i = t >> 3, k = t & 7;
    const float* e = s_eta[g];
    const float* dinv = s_dinv[g];

    float tv = (i == k) ? 1.f : ((i < k) ? e[O_DIM + triu_idx(i, k)] : 0.f);
    float dv = (i == k) ? s_d[g][i] : 0.f;
    float s = 0.f;
#pragma unroll
    for (int j = 0; j < O_DIM; j++) {
        float tji = (j == i) ? 1.f : ((j < i) ? e[O_DIM + triu_idx(j, i)] : 0.f);
        float tjk = (j == k) ? 1.f : ((j < k) ? e[O_DIM + triu_idx(j, k)] : 0.f);
        s = fmaf(tji * tjk, dinv[j], s);
    }

    const size_t base = bh * (O_DIM * O_DIM) + t;
    prec[base] = s;
    Dout[base] = dv;
    Tout[base] = tv;
}

// ---------------------------------------------------------------------------
// Launch
// ---------------------------------------------------------------------------
extern "C" void kernel_launch(void* const* d_in, const int* in_sizes, int n_in,
                              void* d_out, int out_size)
{
    const float* z  = (const float*)d_in[0];
    const float* W1 = (const float*)d_in[1];
    const float* b1 = (const float*)d_in[2];
    const float* W2 = (const float*)d_in[3];
    const float* b2 = (const float*)d_in[4];
    const float* Wm = (const float*)d_in[5];
    const float* bm = (const float*)d_in[6];
    const float* Wv = (const float*)d_in[7];
    const float* bv = (const float*)d_in[8];

    float* out = (float*)d_out;
    const size_t n_means = (size_t)BATCH * FH * O_DIM;
    const size_t n_mat   = (size_t)BATCH * FH * O_DIM * O_DIM;
    float* means = out;
    float* prec  = out + n_means;
    float* Dout  = prec + n_mat;
    float* Tout  = Dout + n_mat;

    __half *zhi, *zlo, *ihi, *ilo, *hhi;
    __half *w1hi, *w2hi, *wchi;
    float *lv, *bcat;
    cudaGetSymbolAddress((void**)&zhi, g_zhi);   cudaGetSymbolAddress((void**)&zlo, g_zlo);
    cudaGetSymbolAddress((void**)&ihi, g_ihi);   cudaGetSymbolAddress((void**)&ilo, g_ilo);
    cudaGetSymbolAddress((void**)&hhi, g_hhi);
    cudaGetSymbolAddress((void**)&w1hi, g_w1hi);
    cudaGetSymbolAddress((void**)&w2hi, g_w2hi);
    cudaGetSymbolAddress((void**)&wchi, g_wchi);
    cudaGetSymbolAddress((void**)&bcat, g_bcat);
    cudaGetSymbolAddress((void**)&lv, g_lv);

    const int SMEM2 = 3 * 30720 + 512;   // 92672 (CTAM=256, PASSES=2)
    const int SMEM1 = 3 * 12288 + 512;   // 37376 (CTAM=128, PASSES=1)
    cudaFuncSetAttribute((void*)gemm_mma<true, 1, 2, 256, 1>,  cudaFuncAttributeMaxDynamicSharedMemorySize, SMEM2);
    cudaFuncSetAttribute((void*)gemm_mma<false, 3, 2, 256, 1>, cudaFuncAttributeMaxDynamicSharedMemorySize, SMEM2);
    cudaFuncSetAttribute((void*)gemm_mma<false, 2, 1, 128, 2>, cudaFuncAttributeMaxDynamicSharedMemorySize, SMEM1);

    // converts (hi-only weights; z keeps hi+lo)
    split_act<<<(BATCH * HID / 4) / 256, 256>>>(z, zhi, zlo);
    split_w<<<dim3(HID / 32, HID / 32), 256>>>(W1, w1hi, HID, HID);
    split_w<<<dim3(HID / 32, HID / 32), 256>>>(W2, w2hi, HID, HID);
    split_w<<<dim3(NM  / 32, HID / 32), 256>>>(Wm, wchi, HID, NM);
    split_w<<<dim3(NV  / 32, HID / 32), 256>>>(Wv, wchi + (size_t)NM * HID, HID, NV);
    concat_bias<<<(NCAT + 255) / 256, 256>>>(bm, bv, bcat);

    // GEMM chain
    gemm_mma<true, 1, 2, 256, 1><<<dim3(HID / 128, BATCH / 256), 256, SMEM2>>>(
        zhi, zlo, w1hi, b1, nullptr, nullptr, ihi, ilo);
    gemm_mma<false, 3, 2, 256, 1><<<dim3(HID / 128, BATCH / 256), 256, SMEM2>>>(
        ihi, ilo, w2hi, b2, nullptr, nullptr, hhi, nullptr);
    gemm_mma<false, 2, 1, 128, 2><<<dim3(NCAT / 128, BATCH / 128), 256, SMEM1>>>(
        hhi, nullptr, wchi, bcat, means, lv, nullptr, nullptr);

    mvn_epilogue<<<(BATCH * FH) / 4, 256>>>(lv, prec, Dout, Tout);
}

// round 12
// speedup vs baseline: 2.1465x; 1.1208x over previous
#include <cuda_runtime.h>
#include <cuda_fp16.h>
#include <math.h>
#include <stdint.h>

#define BATCH 8192
#define HID   1024
#define FH    96
#define O_DIM 8
#define E_DIM 36
#define NM    768
#define NV    3456
#define NCAT  (NM + NV)     // 4224

// ---------------------------------------------------------------------------
// Device scratch (allocation-free per harness rules)
// ---------------------------------------------------------------------------
__device__ __half g_zhi[(size_t)BATCH * HID];
__device__ __half g_zlo[(size_t)BATCH * HID];
__device__ __half g_ihi[(size_t)BATCH * HID];
__device__ __half g_ilo[(size_t)BATCH * HID];
__device__ __half g_hhi[(size_t)BATCH * HID];
__device__ __half g_w1hi[(size_t)HID * HID];
__device__ __half g_w2hi[(size_t)HID * HID];
__device__ __half g_wchi[(size_t)NCAT * HID];   // [Wm|Wv]^T hi
__device__ float  g_bcat[NCAT];
__device__ float  g_lv[(size_t)BATCH * NV];

// ---------------------------------------------------------------------------
// helpers
// ---------------------------------------------------------------------------
__device__ __forceinline__ uint32_t smem_u32(const void* p) {
    uint32_t a;
    asm("{ .reg .u64 t; cvta.to.shared.u64 t, %1; cvt.u32.u64 %0, t; }" : "=r"(a) : "l"(p));
    return a;
}

__device__ __forceinline__ void cp16(uint32_t dst, const void* src) {
    asm volatile("cp.async.cg.shared.global [%0], [%1], 16;" :: "r"(dst), "l"(src));
}
#define CP_COMMIT() asm volatile("cp.async.commit_group;" ::: "memory")
#define CP_WAIT0()  asm volatile("cp.async.wait_group 0;"  ::: "memory")
#define CP_WAIT1()  asm volatile("cp.async.wait_group 1;"  ::: "memory")

__device__ __forceinline__ void ldsm4(uint32_t* r, uint32_t addr) {
    asm volatile("ldmatrix.sync.aligned.m8n8.x4.shared.b16 {%0,%1,%2,%3}, [%4];"
        : "=r"(r[0]), "=r"(r[1]), "=r"(r[2]), "=r"(r[3]) : "r"(addr));
}

__device__ __forceinline__ void mma16816(float* d, const uint32_t* a, const uint32_t* b)
{
    asm volatile(
        "mma.sync.aligned.m16n8k16.row.col.f32.f16.f16.f32 "
        "{%0,%1,%2,%3},{%4,%5,%6,%7},{%8,%9},{%0,%1,%2,%3};\n"
        : "+f"(d[0]), "+f"(d[1]), "+f"(d[2]), "+f"(d[3])
        : "r"(a[0]), "r"(a[1]), "r"(a[2]), "r"(a[3]), "r"(b[0]), "r"(b[1]));
}

__device__ __forceinline__ uint32_t hpack2(float a, float b) {
    __half2 t = __halves2half2(__float2half_rn(a), __float2half_rn(b));
    return *reinterpret_cast<uint32_t*>(&t);
}

// ---------------------------------------------------------------------------
// split_act: fp32 [n] -> hi fp16 [n], lo fp16 [n]
// ---------------------------------------------------------------------------
__global__ __launch_bounds__(256)
void split_act(const float* __restrict__ x,
               __half* __restrict__ hi, __half* __restrict__ lo)
{
    size_t idx = ((size_t)blockIdx.x * blockDim.x + threadIdx.x) * 4;
    float4 v = *(const float4*)(x + idx);
    __half h0 = __float2half_rn(v.x), h1 = __float2half_rn(v.y);
    __half h2 = __float2half_rn(v.z), h3 = __float2half_rn(v.w);
    uint2 hp, lp;
    { __half2 a = __halves2half2(h0, h1), b = __halves2half2(h2, h3);
      hp.x = *(uint32_t*)&a; hp.y = *(uint32_t*)&b; }
    lp.x = hpack2(v.x - __half2float(h0), v.y - __half2float(h1));
    lp.y = hpack2(v.z - __half2float(h2), v.w - __half2float(h3));
    *(uint2*)(hi + idx) = hp;
    *(uint2*)(lo + idx) = lp;
}

// ---------------------------------------------------------------------------
// split_w: W fp32 [K, N] -> Wt hi fp16 [N, K] (transposed, hi only)
// ---------------------------------------------------------------------------
__global__ __launch_bounds__(256)
void split_w(const float* __restrict__ W, __half* __restrict__ Whi, int K, int N)
{
    __shared__ float tile[32][33];
    const int k0 = blockIdx.y * 32, n0 = blockIdx.x * 32;
    const int tx = threadIdx.x & 31, ty = threadIdx.x >> 5;
#pragma unroll
    for (int r = ty; r < 32; r += 8)
        tile[r][tx] = W[(size_t)(k0 + r) * N + n0 + tx];
    __syncthreads();
#pragma unroll
    for (int i = threadIdx.x; i < 32 * 16; i += 256) {
        int nl = i >> 4, kp = i & 15;
        float a = tile[2 * kp][nl], b = tile[2 * kp + 1][nl];
        size_t base = (size_t)(n0 + nl) * K + k0 + 2 * kp;
        *(uint32_t*)(Whi + base) = hpack2(a, b);
    }
}

// concat biases into g_bcat
__global__ void concat_bias(const float* __restrict__ bm, const float* __restrict__ bv,
                            float* __restrict__ bcat)
{
    int i = blockIdx.x * blockDim.x + threadIdx.x;
    if (i < NCAT) bcat[i] = (i < NM) ? bm[i] : bv[i - NM];
}

// ---------------------------------------------------------------------------
// fp16 split GEMM: C[M,N] = act(A @ B_hi^T + bias), A = A_hi (+ A_lo if PASSES==2)
// CTA = CTAM x 128. 8 warps; warp tile = (MT*16) x (NT*8).
// Warp grid: WMCNT = CTAM/(MT*16) along M, 128/(NT*8) along N.
// 3-stage cp.async pipeline, ldmatrix, independent MMA sweeps (no RAW pairs).
// OUTMODE 1: fp16 hi+lo out (Chi/Clo). OUTMODE 3: fp16 hi-only out.
// OUTMODE 2: dual fp32: cols [0,NM) -> Cf0 (stride NM), rest -> Cf1 (stride NV).
// ---------------------------------------------------------------------------
template <bool SILU, int OUTMODE, int PASSES, int CTAM, int MT, int NT, int MINB>
__global__ __launch_bounds__(256, MINB)
void gemm_mma(const __half* __restrict__ Ahi, const __half* __restrict__ Alo,
              const __half* __restrict__ Bthi,
              const float* __restrict__ bias,
              float* __restrict__ Cf0, float* __restrict__ Cf1,
              __half* __restrict__ Chi, __half* __restrict__ Clo)
{
    constexpr int K = HID;
    constexpr int NITER = K / 16;          // 64 k-steps
    constexpr int RS = 48;                 // 16 fp16 = 32B + 16B pad
    constexpr int WMCNT = CTAM / (MT * 16);
    constexpr int SA_HI = 0;
    constexpr int SA_LO = CTAM * RS;
    constexpr int SB_HI = (PASSES == 2) ? (2 * CTAM * RS) : (CTAM * RS);
    constexpr int STAGE = SB_HI + 128 * RS;
    constexpr int BIASOFF = 3 * STAGE;

    extern __shared__ __align__(128) char smem[];
    const uint32_t sb = smem_u32(smem);
    float* sBias = (float*)(smem + BIASOFF);

    const int tid  = threadIdx.x;
    const int lane = tid & 31;
    const int wid  = tid >> 5;
    const int g = lane >> 2;               // 0..7
    const int t = lane & 3;                // 0..3
    const int m0 = (wid % WMCNT) * (MT * 16);
    const int n0 = (wid / WMCNT) * (NT * 8);

    const int blockM = blockIdx.y * CTAM;
    const int blockN = blockIdx.x * 128;

    if (tid < 128) sBias[tid] = bias[blockN + tid];

    // ldmatrix per-lane address offsets (within a stage buffer)
    const uint32_t aoff = (uint32_t)(m0 + (lane & 15)) * RS + (uint32_t)(lane >> 4) * 16;
    const uint32_t boff = (uint32_t)(n0 + ((lane >> 4) << 3) + (lane & 7)) * RS
                        + (uint32_t)((lane >> 3) & 1) * 16;

    const __half* Ahi_b = Ahi + (size_t)blockM * K;
    const __half* Alo_b = (PASSES == 2) ? (Alo + (size_t)blockM * K) : nullptr;
    const __half* Bhi_b = Bthi + (size_t)blockN * K;

    auto load_stage = [&](int s) {
        const int k0 = s * 16;
        const uint32_t buf = sb + (s % 3) * STAGE;
#pragma unroll
        for (int j = 0; j < CTAM / 128; j++) {
            const int idx = tid + 256 * j;
            const int row = idx >> 1, ch = idx & 1;
            const size_t goff = (size_t)row * K + k0 + ch * 8;
            const uint32_t soff = row * RS + ch * 16;
            cp16(buf + SA_HI + soff, Ahi_b + goff);
            if (PASSES == 2)
                cp16(buf + SA_LO + soff, Alo_b + goff);
        }
        {
            const int row = tid >> 1, ch = tid & 1;
            const size_t goff = (size_t)row * K + k0 + ch * 8;
            const uint32_t soff = row * RS + ch * 16;
            cp16(buf + SB_HI + soff, Bhi_b + goff);
        }
    };

    float acc[MT][NT][4];
#pragma unroll
    for (int mt = 0; mt < MT; mt++)
#pragma unroll
        for (int nt = 0; nt < NT; nt++)
#pragma unroll
            for (int c = 0; c < 4; c++) acc[mt][nt][c] = 0.f;

    load_stage(0); CP_COMMIT();
    load_stage(1); CP_COMMIT();

    for (int it = 0; it < NITER; ++it) {
        if (it == NITER - 1) { CP_WAIT0(); } else { CP_WAIT1(); }
        __syncthreads();
        if (it + 2 < NITER) { load_stage(it + 2); CP_COMMIT(); }

        const uint32_t buf = sb + (it % 3) * STAGE;
        const uint32_t aHi = buf + SA_HI + aoff;
        const uint32_t aLo = buf + SA_LO + aoff;
        const uint32_t bHi = buf + SB_HI + boff;

        uint32_t fAhi[MT][4], fAlo[MT][4], fBhi[NT][2];
#pragma unroll
        for (int mt = 0; mt < MT; mt++) {
            ldsm4(fAhi[mt], aHi + mt * 16 * RS);
            if (PASSES == 2)
                ldsm4(fAlo[mt], aLo + mt * 16 * RS);
        }
#pragma unroll
        for (int nt = 0; nt < NT; nt += 2)
            ldsm4(&fBhi[nt][0], bHi + nt * 8 * RS);

        // independent sweeps: each acc tile touched many MMAs apart
#pragma unroll
        for (int mt = 0; mt < MT; mt++)
#pragma unroll
            for (int nt = 0; nt < NT; nt++)
                mma16816(acc[mt][nt], fAhi[mt], fBhi[nt]);
        if (PASSES == 2) {
#pragma unroll
            for (int mt = 0; mt < MT; mt++)
#pragma unroll
                for (int nt = 0; nt < NT; nt++)
                    mma16816(acc[mt][nt], fAlo[mt], fBhi[nt]);
        }
    }

    // output target for OUTMODE 2 (block never straddles NM boundary: 768 % 128 == 0)
    float* Cout = nullptr;
    int cstride = 0, cbase = 0;
    if (OUTMODE == 2) {
        if (blockN < NM) { Cout = Cf0; cstride = NM; cbase = blockN; }
        else             { Cout = Cf1; cstride = NV; cbase = blockN - NM; }
    }

    // epilogue
#pragma unroll
    for (int mt = 0; mt < MT; mt++) {
        const int row0 = blockM + m0 + mt * 16 + g;
#pragma unroll
        for (int nt = 0; nt < NT; nt++) {
            const int coll = n0 + nt * 8 + 2 * t;
            const float bv0 = sBias[coll], bv1 = sBias[coll + 1];
            float v00 = acc[mt][nt][0] + bv0, v01 = acc[mt][nt][1] + bv1;
            float v10 = acc[mt][nt][2] + bv0, v11 = acc[mt][nt][3] + bv1;
            if (SILU) {
                v00 = v00 / (1.f + expf(-v00));
                v01 = v01 / (1.f + expf(-v01));
                v10 = v10 / (1.f + expf(-v10));
                v11 = v11 / (1.f + expf(-v11));
            }
            if (OUTMODE == 2) {
                const int col = cbase + coll;
                float2 a = {v00, v01}, b = {v10, v11};
                *(float2*)(Cout + (size_t)row0 * cstride + col)       = a;
                *(float2*)(Cout + (size_t)(row0 + 8) * cstride + col) = b;
            } else {
                const int col = blockN + coll;
                __half h00 = __float2half_rn(v00), h01 = __float2half_rn(v01);
                __half h10 = __float2half_rn(v10), h11 = __float2half_rn(v11);
                size_t p0 = (size_t)row0 * HID + col;
                size_t p1 = (size_t)(row0 + 8) * HID + col;
                { __half2 x = __halves2half2(h00, h01);
                  *(uint32_t*)(Chi + p0) = *(uint32_t*)&x; }
                { __half2 x = __halves2half2(h10, h11);
                  *(uint32_t*)(Chi + p1) = *(uint32_t*)&x; }
                if (OUTMODE == 1) {
                    *(uint32_t*)(Clo + p0) = hpack2(v00 - __half2float(h00), v01 - __half2float(h01));
                    *(uint32_t*)(Clo + p1) = hpack2(v10 - __half2float(h10), v11 - __half2float(h11));
                }
            }
        }
    }
}

// ---------------------------------------------------------------------------
// MVN epilogue
// ---------------------------------------------------------------------------
__device__ __forceinline__ int triu_idx(int r, int c) {
    return r * (15 - r) / 2 + (c - r - 1);
}

__global__ __launch_bounds__(256)
void mvn_epilogue(const float* __restrict__ lv,
                  float* __restrict__ prec,
                  float* __restrict__ Dout,
                  float* __restrict__ Tout)
{
    constexpr int GP = 4;
    __shared__ float s_eta[GP][E_DIM];
    __shared__ float s_d[GP][O_DIM];
    __shared__ float s_dinv[GP][O_DIM];

    const int g = threadIdx.x >> 6;
    const int t = threadIdx.x & 63;
    const size_t bh = (size_t)blockIdx.x * GP + g;

    if (t < E_DIM) s_eta[g][t] = lv[bh * E_DIM + t];
    __syncthreads();
    if (t < O_DIM) {
        float d = expf(0.5f * s_eta[g][t]);
        s_d[g][t] = d;
        s_dinv[g][t] = 1.f / d;
    }
    __syncthreads();

    const int i = t >> 3, k = t & 7;
    const float* e = s_eta[g];
    const float* dinv = s_dinv[g];

    float tv = (i == k) ? 1.f : ((i < k) ? e[O_DIM + triu_idx(i, k)] : 0.f);
    float dv = (i == k) ? s_d[g][i] : 0.f;
    float s = 0.f;
#pragma unroll
    for (int j = 0; j < O_DIM; j++) {
        float tji = (j == i) ? 1.f : ((j < i) ? e[O_DIM + triu_idx(j, i)] : 0.f);
        float tjk = (j == k) ? 1.f : ((j < k) ? e[O_DIM + triu_idx(j, k)] : 0.f);
        s = fmaf(tji * tjk, dinv[j], s);
    }

    const size_t base = bh * (O_DIM * O_DIM) + t;
    prec[base] = s;
    Dout[base] = dv;
    Tout[base] = tv;
}

// ---------------------------------------------------------------------------
// Launch
// ---------------------------------------------------------------------------
extern "C" void kernel_launch(void* const* d_in, const int* in_sizes, int n_in,
                              void* d_out, int out_size)
{
    const float* z  = (const float*)d_in[0];
    const float* W1 = (const float*)d_in[1];
    const float* b1 = (const float*)d_in[2];
    const float* W2 = (const float*)d_in[3];
    const float* b2 = (const float*)d_in[4];
    const float* Wm = (const float*)d_in[5];
    const float* bm = (const float*)d_in[6];
    const float* Wv = (const float*)d_in[7];
    const float* bv = (const float*)d_in[8];

    float* out = (float*)d_out;
    const size_t n_means = (size_t)BATCH * FH * O_DIM;
    const size_t n_mat   = (size_t)BATCH * FH * O_DIM * O_DIM;
    float* means = out;
    float* prec  = out + n_means;
    float* Dout  = prec + n_mat;
    float* Tout  = Dout + n_mat;

    __half *zhi, *zlo, *ihi, *ilo, *hhi;
    __half *w1hi, *w2hi, *wchi;
    float *lv, *bcat;
    cudaGetSymbolAddress((void**)&zhi, g_zhi);   cudaGetSymbolAddress((void**)&zlo, g_zlo);
    cudaGetSymbolAddress((void**)&ihi, g_ihi);   cudaGetSymbolAddress((void**)&ilo, g_ilo);
    cudaGetSymbolAddress((void**)&hhi, g_hhi);
    cudaGetSymbolAddress((void**)&w1hi, g_w1hi);
    cudaGetSymbolAddress((void**)&w2hi, g_w2hi);
    cudaGetSymbolAddress((void**)&wchi, g_wchi);
    cudaGetSymbolAddress((void**)&bcat, g_bcat);
    cudaGetSymbolAddress((void**)&lv, g_lv);

    // GEMM1/2: CTA 128x128, warp 32x64 (MT2 NT8), PASSES=2, 2 CTAs/SM
    const int SMEM12 = 3 * 18432 + 512;   // 55808
    // GEMM3:   CTA 128x128, warp 64x32 (MT4 NT4), PASSES=1, 2 CTAs/SM
    const int SMEM3  = 3 * 12288 + 512;   // 37376
    cudaFuncSetAttribute((void*)gemm_mma<true, 1, 2, 128, 2, 8, 2>,  cudaFuncAttributeMaxDynamicSharedMemorySize, SMEM12);
    cudaFuncSetAttribute((void*)gemm_mma<false, 3, 2, 128, 2, 8, 2>, cudaFuncAttributeMaxDynamicSharedMemorySize, SMEM12);
    cudaFuncSetAttribute((void*)gemm_mma<false, 2, 1, 128, 4, 4, 2>, cudaFuncAttributeMaxDynamicSharedMemorySize, SMEM3);

    // converts (hi-only weights; z keeps hi+lo)
    split_act<<<(BATCH * HID / 4) / 256, 256>>>(z, zhi, zlo);
    split_w<<<dim3(HID / 32, HID / 32), 256>>>(W1, w1hi, HID, HID);
    split_w<<<dim3(HID / 32, HID / 32), 256>>>(W2, w2hi, HID, HID);
    split_w<<<dim3(NM  / 32, HID / 32), 256>>>(Wm, wchi, HID, NM);
    split_w<<<dim3(NV  / 32, HID / 32), 256>>>(Wv, wchi + (size_t)NM * HID, HID, NV);
    concat_bias<<<(NCAT + 255) / 256, 256>>>(bm, bv, bcat);

    // GEMM chain
    gemm_mma<true, 1, 2, 128, 2, 8, 2><<<dim3(HID / 128, BATCH / 128), 256, SMEM12>>>(
        zhi, zlo, w1hi, b1, nullptr, nullptr, ihi, ilo);
    gemm_mma<false, 3, 2, 128, 2, 8, 2><<<dim3(HID / 128, BATCH / 128), 256, SMEM12>>>(
        ihi, ilo, w2hi, b2, nullptr, nullptr, hhi, nullptr);
    gemm_mma<false, 2, 1, 128, 4, 4, 2><<<dim3(NCAT / 128, BATCH / 128), 256, SMEM3>>>(
        hhi, nullptr, wchi, bcat, means, lv, nullptr, nullptr);

    mvn_epilogue<<<(BATCH * FH) / 4, 256>>>(lv, prec, Dout, Tout);
}

// round 13
// speedup vs baseline: 3.2521x; 1.5150x over previous
#include <cuda_runtime.h>
#include <cuda_fp16.h>
#include <math.h>
#include <stdint.h>

#define BATCH 8192
#define HID   1024
#define FH    96
#define O_DIM 8
#define E_DIM 36
#define NM    768
#define NV    3456
#define NCAT  (NM + NV)     // 4224

// ---------------------------------------------------------------------------
// Device scratch (allocation-free per harness rules)
// ---------------------------------------------------------------------------
__device__ __half g_zhi[(size_t)BATCH * HID];
__device__ __half g_ihi[(size_t)BATCH * HID];
__device__ __half g_hhi[(size_t)BATCH * HID];
__device__ __half g_w1hi[(size_t)HID * HID];
__device__ __half g_w2hi[(size_t)HID * HID];
__device__ __half g_wchi[(size_t)NCAT * HID];   // [Wm|Wv]^T hi
__device__ float  g_bcat[NCAT];
__device__ float  g_lv[(size_t)BATCH * NV];

// ---------------------------------------------------------------------------
// helpers
// ---------------------------------------------------------------------------
__device__ __forceinline__ uint32_t smem_u32(const void* p) {
    uint32_t a;
    asm("{ .reg .u64 t; cvta.to.shared.u64 t, %1; cvt.u32.u64 %0, t; }" : "=r"(a) : "l"(p));
    return a;
}

__device__ __forceinline__ void cp16(uint32_t dst, const void* src) {
    asm volatile("cp.async.cg.shared.global [%0], [%1], 16;" :: "r"(dst), "l"(src));
}
#define CP_COMMIT() asm volatile("cp.async.commit_group;" ::: "memory")
#define CP_WAIT0()  asm volatile("cp.async.wait_group 0;"  ::: "memory")
#define CP_WAIT1()  asm volatile("cp.async.wait_group 1;"  ::: "memory")

__device__ __forceinline__ void ldsm4(uint32_t* r, uint32_t addr) {
    asm volatile("ldmatrix.sync.aligned.m8n8.x4.shared.b16 {%0,%1,%2,%3}, [%4];"
        : "=r"(r[0]), "=r"(r[1]), "=r"(r[2]), "=r"(r[3]) : "r"(addr));
}

__device__ __forceinline__ void mma16816(float* d, const uint32_t* a, const uint32_t* b)
{
    asm volatile(
        "mma.sync.aligned.m16n8k16.row.col.f32.f16.f16.f32 "
        "{%0,%1,%2,%3},{%4,%5,%6,%7},{%8,%9},{%0,%1,%2,%3};\n"
        : "+f"(d[0]), "+f"(d[1]), "+f"(d[2]), "+f"(d[3])
        : "r"(a[0]), "r"(a[1]), "r"(a[2]), "r"(a[3]), "r"(b[0]), "r"(b[1]));
}

__device__ __forceinline__ uint32_t hpack2(float a, float b) {
    __half2 t = __halves2half2(__float2half_rn(a), __float2half_rn(b));
    return *reinterpret_cast<uint32_t*>(&t);
}

// ---------------------------------------------------------------------------
// cvt_act: fp32 [n] -> fp16 hi [n]
// ---------------------------------------------------------------------------
__global__ __launch_bounds__(256)
void cvt_act(const float* __restrict__ x, __half* __restrict__ hi)
{
    size_t idx = ((size_t)blockIdx.x * blockDim.x + threadIdx.x) * 4;
    float4 v = *(const float4*)(x + idx);
    uint2 hp;
    hp.x = hpack2(v.x, v.y);
    hp.y = hpack2(v.z, v.w);
    *(uint2*)(hi + idx) = hp;
}

// ---------------------------------------------------------------------------
// split_w: W fp32 [K, N] -> Wt hi fp16 [N, K] (transposed, hi only)
// ---------------------------------------------------------------------------
__global__ __launch_bounds__(256)
void split_w(const float* __restrict__ W, __half* __restrict__ Whi, int K, int N)
{
    __shared__ float tile[32][33];
    const int k0 = blockIdx.y * 32, n0 = blockIdx.x * 32;
    const int tx = threadIdx.x & 31, ty = threadIdx.x >> 5;
#pragma unroll
    for (int r = ty; r < 32; r += 8)
        tile[r][tx] = W[(size_t)(k0 + r) * N + n0 + tx];
    __syncthreads();
#pragma unroll
    for (int i = threadIdx.x; i < 32 * 16; i += 256) {
        int nl = i >> 4, kp = i & 15;
        float a = tile[2 * kp][nl], b = tile[2 * kp + 1][nl];
        size_t base = (size_t)(n0 + nl) * K + k0 + 2 * kp;
        *(uint32_t*)(Whi + base) = hpack2(a, b);
    }
}

// concat biases into g_bcat
__global__ void concat_bias(const float* __restrict__ bm, const float* __restrict__ bv,
                            float* __restrict__ bcat)
{
    int i = blockIdx.x * blockDim.x + threadIdx.x;
    if (i < NCAT) bcat[i] = (i < NM) ? bm[i] : bv[i - NM];
}

// ---------------------------------------------------------------------------
// fp16 GEMM: C[M,N] = act(A_hi @ B_hi^T + bias)   (single pass)
// CTA 128x128, 8 warps 2Mx4N, warp 64x32 (MT4 NT4). 2 CTAs/SM.
// 3-stage cp.async pipeline, ldmatrix, independent MMA sweeps.
// OUTMODE 3: fp16 out (Chi), N must be HID.
// OUTMODE 2: dual fp32: cols [0,NM) -> Cf0 (stride NM), rest -> Cf1 (stride NV).
// ---------------------------------------------------------------------------
template <bool SILU, int OUTMODE>
__global__ __launch_bounds__(256, 2)
void gemm_mma(const __half* __restrict__ Ahi,
              const __half* __restrict__ Bthi,
              const float* __restrict__ bias,
              float* __restrict__ Cf0, float* __restrict__ Cf1,
              __half* __restrict__ Chi)
{
    constexpr int K = HID;
    constexpr int NITER = K / 16;          // 64 k-steps
    constexpr int RS = 48;                 // 16 fp16 = 32B + 16B pad
    constexpr int MT = 4, NT = 4;
    constexpr int CTAM = 128;
    constexpr int WMCNT = CTAM / (MT * 16);    // 2
    constexpr int SA_HI = 0;
    constexpr int SB_HI = CTAM * RS;           // 6144
    constexpr int STAGE = SB_HI + 128 * RS;    // 12288
    constexpr int BIASOFF = 3 * STAGE;

    extern __shared__ __align__(128) char smem[];
    const uint32_t sb = smem_u32(smem);
    float* sBias = (float*)(smem + BIASOFF);

    const int tid  = threadIdx.x;
    const int lane = tid & 31;
    const int wid  = tid >> 5;
    const int g = lane >> 2;               // 0..7
    const int t = lane & 3;                // 0..3
    const int m0 = (wid % WMCNT) * (MT * 16);
    const int n0 = (wid / WMCNT) * (NT * 8);

    const int blockM = blockIdx.y * CTAM;
    const int blockN = blockIdx.x * 128;

    if (tid < 128) sBias[tid] = bias[blockN + tid];

    const uint32_t aoff = (uint32_t)(m0 + (lane & 15)) * RS + (uint32_t)(lane >> 4) * 16;
    const uint32_t boff = (uint32_t)(n0 + ((lane >> 4) << 3) + (lane & 7)) * RS
                        + (uint32_t)((lane >> 3) & 1) * 16;

    const __half* Ahi_b = Ahi + (size_t)blockM * K;
    const __half* Bhi_b = Bthi + (size_t)blockN * K;

    auto load_stage = [&](int s) {
        const int k0 = s * 16;
        const uint32_t buf = sb + (s % 3) * STAGE;
        const int row = tid >> 1, ch = tid & 1;
        const size_t goff = (size_t)row * K + k0 + ch * 8;
        const uint32_t soff = row * RS + ch * 16;
        cp16(buf + SA_HI + soff, Ahi_b + goff);
        cp16(buf + SB_HI + soff, Bhi_b + goff);
    };

    float acc[MT][NT][4];
#pragma unroll
    for (int mt = 0; mt < MT; mt++)
#pragma unroll
        for (int nt = 0; nt < NT; nt++)
#pragma unroll
            for (int c = 0; c < 4; c++) acc[mt][nt][c] = 0.f;

    load_stage(0); CP_COMMIT();
    load_stage(1); CP_COMMIT();

    for (int it = 0; it < NITER; ++it) {
        if (it == NITER - 1) { CP_WAIT0(); } else { CP_WAIT1(); }
        __syncthreads();
        if (it + 2 < NITER) { load_stage(it + 2); CP_COMMIT(); }

        const uint32_t buf = sb + (it % 3) * STAGE;
        const uint32_t aHi = buf + SA_HI + aoff;
        const uint32_t bHi = buf + SB_HI + boff;

        uint32_t fAhi[MT][4], fBhi[NT][2];
#pragma unroll
        for (int mt = 0; mt < MT; mt++)
            ldsm4(fAhi[mt], aHi + mt * 16 * RS);
#pragma unroll
        for (int nt = 0; nt < NT; nt += 2)
            ldsm4(&fBhi[nt][0], bHi + nt * 8 * RS);

#pragma unroll
        for (int mt = 0; mt < MT; mt++)
#pragma unroll
            for (int nt = 0; nt < NT; nt++)
                mma16816(acc[mt][nt], fAhi[mt], fBhi[nt]);
    }

    // output target for OUTMODE 2 (block never straddles NM boundary: 768 % 128 == 0)
    float* Cout = nullptr;
    int cstride = 0, cbase = 0;
    if (OUTMODE == 2) {
        if (blockN < NM) { Cout = Cf0; cstride = NM; cbase = blockN; }
        else             { Cout = Cf1; cstride = NV; cbase = blockN - NM; }
    }

    // epilogue
#pragma unroll
    for (int mt = 0; mt < MT; mt++) {
        const int row0 = blockM + m0 + mt * 16 + g;
#pragma unroll
        for (int nt = 0; nt < NT; nt++) {
            const int coll = n0 + nt * 8 + 2 * t;
            const float bv0 = sBias[coll], bv1 = sBias[coll + 1];
            float v00 = acc[mt][nt][0] + bv0, v01 = acc[mt][nt][1] + bv1;
            float v10 = acc[mt][nt][2] + bv0, v11 = acc[mt][nt][3] + bv1;
            if (SILU) {
                v00 = v00 / (1.f + expf(-v00));
                v01 = v01 / (1.f + expf(-v01));
                v10 = v10 / (1.f + expf(-v10));
                v11 = v11 / (1.f + expf(-v11));
            }
            if (OUTMODE == 2) {
                const int col = cbase + coll;
                float2 a = {v00, v01}, b = {v10, v11};
                *(float2*)(Cout + (size_t)row0 * cstride + col)       = a;
                *(float2*)(Cout + (size_t)(row0 + 8) * cstride + col) = b;
            } else {
                const int col = blockN + coll;
                size_t p0 = (size_t)row0 * HID + col;
                size_t p1 = (size_t)(row0 + 8) * HID + col;
                *(uint32_t*)(Chi + p0) = hpack2(v00, v01);
                *(uint32_t*)(Chi + p1) = hpack2(v10, v11);
            }
        }
    }
}

// ---------------------------------------------------------------------------
// MVN epilogue: 16 threads per (b,h) group, float4 stores.
// ---------------------------------------------------------------------------
__device__ __forceinline__ int triu_idx(int r, int c) {
    return r * (15 - r) / 2 + (c - r - 1);
}

__global__ __launch_bounds__(256)
void mvn_epilogue(const float* __restrict__ lv,
                  float* __restrict__ prec,
                  float* __restrict__ Dout,
                  float* __restrict__ Tout)
{
    constexpr int GP = 16;                 // groups per block (16 threads each)
    __shared__ float s_eta[GP][E_DIM];
    __shared__ float s_d[GP][O_DIM];
    __shared__ float s_dinv[GP][O_DIM];

    const int g = threadIdx.x >> 4;        // 0..15
    const int s = threadIdx.x & 15;        // 0..15
    const size_t bh = (size_t)blockIdx.x * GP + g;

#pragma unroll
    for (int e = s; e < E_DIM; e += 16)
        s_eta[g][e] = lv[bh * E_DIM + e];
    __syncthreads();
    if (s < O_DIM) {
        float d = expf(0.5f * s_eta[g][s]);
        s_d[g][s] = d;
        s_dinv[g][s] = 1.f / d;
    }
    __syncthreads();

    const int i  = s >> 1;                 // row 0..7
    const int kb = (s & 1) * 4;            // col base 0 or 4
    const float* e = s_eta[g];
    const float* dinv = s_dinv[g];

    float pv[4] = {0.f, 0.f, 0.f, 0.f};
    float tv[4], dv[4];
#pragma unroll
    for (int c = 0; c < 4; c++) {
        const int k = kb + c;
        tv[c] = (i == k) ? 1.f : ((i < k) ? e[O_DIM + triu_idx(i, k)] : 0.f);
        dv[c] = (i == k) ? s_d[g][i] : 0.f;
    }
#pragma unroll
    for (int j = 0; j < O_DIM; j++) {
        float tji = (j == i) ? 1.f : ((j < i) ? e[O_DIM + triu_idx(j, i)] : 0.f);
        float w = tji * dinv[j];
#pragma unroll
        for (int c = 0; c < 4; c++) {
            const int k = kb + c;
            float tjk = (j == k) ? 1.f : ((j < k) ? e[O_DIM + triu_idx(j, k)] : 0.f);
            pv[c] = fmaf(w, tjk, pv[c]);
        }
    }

    const size_t base = bh * (O_DIM * O_DIM) + i * O_DIM + kb;
    *(float4*)(prec + base) = *(float4*)pv;
    *(float4*)(Dout + base) = *(float4*)dv;
    *(float4*)(Tout + base) = *(float4*)tv;
}

// ---------------------------------------------------------------------------
// Launch
// ---------------------------------------------------------------------------
extern "C" void kernel_launch(void* const* d_in, const int* in_sizes, int n_in,
                              void* d_out, int out_size)
{
    const float* z  = (const float*)d_in[0];
    const float* W1 = (const float*)d_in[1];
    const float* b1 = (const float*)d_in[2];
    const float* W2 = (const float*)d_in[3];
    const float* b2 = (const float*)d_in[4];
    const float* Wm = (const float*)d_in[5];
    const float* bm = (const float*)d_in[6];
    const float* Wv = (const float*)d_in[7];
    const float* bv = (const float*)d_in[8];

    float* out = (float*)d_out;
    const size_t n_means = (size_t)BATCH * FH * O_DIM;
    const size_t n_mat   = (size_t)BATCH * FH * O_DIM * O_DIM;
    float* means = out;
    float* prec  = out + n_means;
    float* Dout  = prec + n_mat;
    float* Tout  = Dout + n_mat;

    __half *zhi, *ihi, *hhi, *w1hi, *w2hi, *wchi;
    float *lv, *bcat;
    cudaGetSymbolAddress((void**)&zhi, g_zhi);
    cudaGetSymbolAddress((void**)&ihi, g_ihi);
    cudaGetSymbolAddress((void**)&hhi, g_hhi);
    cudaGetSymbolAddress((void**)&w1hi, g_w1hi);
    cudaGetSymbolAddress((void**)&w2hi, g_w2hi);
    cudaGetSymbolAddress((void**)&wchi, g_wchi);
    cudaGetSymbolAddress((void**)&bcat, g_bcat);
    cudaGetSymbolAddress((void**)&lv, g_lv);

    const int SMEM = 3 * 12288 + 512;   // 37376
    cudaFuncSetAttribute((void*)gemm_mma<true, 3>,  cudaFuncAttributeMaxDynamicSharedMemorySize, SMEM);
    cudaFuncSetAttribute((void*)gemm_mma<false, 3>, cudaFuncAttributeMaxDynamicSharedMemorySize, SMEM);
    cudaFuncSetAttribute((void*)gemm_mma<false, 2>, cudaFuncAttributeMaxDynamicSharedMemorySize, SMEM);

    // converts (hi-only everywhere)
    cvt_act<<<(BATCH * HID / 4) / 256, 256>>>(z, zhi);
    split_w<<<dim3(HID / 32, HID / 32), 256>>>(W1, w1hi, HID, HID);
    split_w<<<dim3(HID / 32, HID / 32), 256>>>(W2, w2hi, HID, HID);
    split_w<<<dim3(NM  / 32, HID / 32), 256>>>(Wm, wchi, HID, NM);
    split_w<<<dim3(NV  / 32, HID / 32), 256>>>(Wv, wchi + (size_t)NM * HID, HID, NV);
    concat_bias<<<(NCAT + 255) / 256, 256>>>(bm, bv, bcat);

    // GEMM chain (all single-pass fp16, CTA 128x128, 2 CTAs/SM)
    gemm_mma<true, 3><<<dim3(HID / 128, BATCH / 128), 256, SMEM>>>(
        zhi, w1hi, b1, nullptr, nullptr, ihi);
    gemm_mma<false, 3><<<dim3(HID / 128, BATCH / 128), 256, SMEM>>>(
        ihi, w2hi, b2, nullptr, nullptr, hhi);
    gemm_mma<false, 2><<<dim3(NCAT / 128, BATCH / 128), 256, SMEM>>>(
        hhi, wchi, bcat, means, lv, nullptr);

    // MVN epilogue (16 groups/block, float4 stores)
    mvn_epilogue<<<(BATCH * FH) / 16, 256>>>(lv, prec, Dout, Tout);
}

// round 14
// speedup vs baseline: 3.2571x; 1.0015x over previous
#include <cuda_runtime.h>
#include <cuda_fp16.h>
#include <math.h>
#include <stdint.h>

#define BATCH 8192
#define HID   1024
#define FH    96
#define O_DIM 8
#define E_DIM 36
#define NM    768
#define NV    3456
#define NCAT  (NM + NV)     // 4224

// ---------------------------------------------------------------------------
// Device scratch (allocation-free per harness rules)
// ---------------------------------------------------------------------------
__device__ __half g_zhi[(size_t)BATCH * HID];
__device__ __half g_ihi[(size_t)BATCH * HID];
__device__ __half g_hhi[(size_t)BATCH * HID];
__device__ __half g_w1hi[(size_t)HID * HID];
__device__ __half g_w2hi[(size_t)HID * HID];
__device__ __half g_wchi[(size_t)NCAT * HID];   // [Wm|Wv]^T hi
__device__ float  g_bcat[NCAT];
__device__ float  g_lv[(size_t)BATCH * NV];

// ---------------------------------------------------------------------------
// helpers
// ---------------------------------------------------------------------------
__device__ __forceinline__ uint32_t smem_u32(const void* p) {
    uint32_t a;
    asm("{ .reg .u64 t; cvta.to.shared.u64 t, %1; cvt.u32.u64 %0, t; }" : "=r"(a) : "l"(p));
    return a;
}

__device__ __forceinline__ void cp16(uint32_t dst, const void* src) {
    asm volatile("cp.async.cg.shared.global [%0], [%1], 16;" :: "r"(dst), "l"(src));
}
#define CP_COMMIT() asm volatile("cp.async.commit_group;" ::: "memory")
#define CP_WAIT0()  asm volatile("cp.async.wait_group 0;"  ::: "memory")
#define CP_WAIT1()  asm volatile("cp.async.wait_group 1;"  ::: "memory")

__device__ __forceinline__ void ldsm4(uint32_t* r, uint32_t addr) {
    asm volatile("ldmatrix.sync.aligned.m8n8.x4.shared.b16 {%0,%1,%2,%3}, [%4];"
        : "=r"(r[0]), "=r"(r[1]), "=r"(r[2]), "=r"(r[3]) : "r"(addr));
}

__device__ __forceinline__ void mma16816(float* d, const uint32_t* a, const uint32_t* b)
{
    asm volatile(
        "mma.sync.aligned.m16n8k16.row.col.f32.f16.f16.f32 "
        "{%0,%1,%2,%3},{%4,%5,%6,%7},{%8,%9},{%0,%1,%2,%3};\n"
        : "+f"(d[0]), "+f"(d[1]), "+f"(d[2]), "+f"(d[3])
        : "r"(a[0]), "r"(a[1]), "r"(a[2]), "r"(a[3]), "r"(b[0]), "r"(b[1]));
}

__device__ __forceinline__ uint32_t hpack2(float a, float b) {
    __half2 t = __halves2half2(__float2half_rn(a), __float2half_rn(b));
    return *reinterpret_cast<uint32_t*>(&t);
}

// ---------------------------------------------------------------------------
// cvt_act: fp32 [n] -> fp16 hi [n]
// ---------------------------------------------------------------------------
__global__ __launch_bounds__(256)
void cvt_act(const float* __restrict__ x, __half* __restrict__ hi)
{
    size_t idx = ((size_t)blockIdx.x * blockDim.x + threadIdx.x) * 4;
    float4 v = *(const float4*)(x + idx);
    uint2 hp;
    hp.x = hpack2(v.x, v.y);
    hp.y = hpack2(v.z, v.w);
    *(uint2*)(hi + idx) = hp;
}

// ---------------------------------------------------------------------------
// convert all weights in ONE launch:
//   x-tiles: [0,32) W1 | [32,64) W2 | [64,88) Wm -> wc | [88,196) Wv -> wc+NM*K
// Each produces Wt fp16 [N, K] (transposed). K = HID for all.
// ---------------------------------------------------------------------------
__global__ __launch_bounds__(256)
void convert_w_all(const float* __restrict__ W1, const float* __restrict__ W2,
                   const float* __restrict__ Wm, const float* __restrict__ Wv,
                   __half* __restrict__ w1t, __half* __restrict__ w2t,
                   __half* __restrict__ wct)
{
    constexpr int K = HID;
    const int bx = blockIdx.x;
    const float* W; __half* Wt; int N; int xt;
    if (bx < 32)       { W = W1; Wt = w1t; N = HID; xt = bx; }
    else if (bx < 64)  { W = W2; Wt = w2t; N = HID; xt = bx - 32; }
    else if (bx < 88)  { W = Wm; Wt = wct; N = NM;  xt = bx - 64; }
    else               { W = Wv; Wt = wct + (size_t)NM * K; N = NV; xt = bx - 88; }

    __shared__ float tile[32][33];
    const int k0 = blockIdx.y * 32, n0 = xt * 32;
    const int tx = threadIdx.x & 31, ty = threadIdx.x >> 5;
#pragma unroll
    for (int r = ty; r < 32; r += 8)
        tile[r][tx] = W[(size_t)(k0 + r) * N + n0 + tx];
    __syncthreads();
#pragma unroll
    for (int i = threadIdx.x; i < 32 * 16; i += 256) {
        int nl = i >> 4, kp = i & 15;
        float a = tile[2 * kp][nl], b = tile[2 * kp + 1][nl];
        size_t base = (size_t)(n0 + nl) * K + k0 + 2 * kp;
        *(uint32_t*)(Wt + base) = hpack2(a, b);
    }
}

// concat biases into g_bcat
__global__ void concat_bias(const float* __restrict__ bm, const float* __restrict__ bv,
                            float* __restrict__ bcat)
{
    int i = blockIdx.x * blockDim.x + threadIdx.x;
    if (i < NCAT) bcat[i] = (i < NM) ? bm[i] : bv[i - NM];
}

// ---------------------------------------------------------------------------
// fp16 GEMM: C[M,N] = act(A_hi @ B_hi^T + bias)   (single pass, BK=32)
// CTA 128x128, 8 warps 2Mx4N, warp 64x32 (MT4 NT4). 2 CTAs/SM.
// 3-stage cp.async pipeline (BK=32 each), ldmatrix, independent MMA sweeps.
// OUTMODE 3: fp16 out (Chi), N must be HID.
// OUTMODE 2: dual fp32: cols [0,NM) -> Cf0 (stride NM), rest -> Cf1 (stride NV).
// ---------------------------------------------------------------------------
template <bool SILU, int OUTMODE>
__global__ __launch_bounds__(256, 2)
void gemm_mma(const __half* __restrict__ Ahi,
              const __half* __restrict__ Bthi,
              const float* __restrict__ bias,
              float* __restrict__ Cf0, float* __restrict__ Cf1,
              __half* __restrict__ Chi)
{
    constexpr int K = HID;
    constexpr int BK = 32;
    constexpr int NITER = K / BK;          // 32 stages
    constexpr int RS = 80;                 // 32 fp16 = 64B + 16B pad
    constexpr int MT = 4, NT = 4;
    constexpr int CTAM = 128;
    constexpr int WMCNT = CTAM / (MT * 16);    // 2
    constexpr int SA_HI = 0;
    constexpr int SB_HI = CTAM * RS;           // 10240
    constexpr int STAGE = SB_HI + 128 * RS;    // 20480
    constexpr int BIASOFF = 3 * STAGE;         // 61440

    extern __shared__ __align__(128) char smem[];
    const uint32_t sb = smem_u32(smem);
    float* sBias = (float*)(smem + BIASOFF);

    const int tid  = threadIdx.x;
    const int lane = tid & 31;
    const int wid  = tid >> 5;
    const int g = lane >> 2;               // 0..7
    const int t = lane & 3;                // 0..3
    const int m0 = (wid % WMCNT) * (MT * 16);
    const int n0 = (wid / WMCNT) * (NT * 8);

    const int blockM = blockIdx.y * CTAM;
    const int blockN = blockIdx.x * 128;

    if (tid < 128) sBias[tid] = bias[blockN + tid];

    const uint32_t aoff = (uint32_t)(m0 + (lane & 15)) * RS + (uint32_t)(lane >> 4) * 16;
    const uint32_t boff = (uint32_t)(n0 + ((lane >> 4) << 3) + (lane & 7)) * RS
                        + (uint32_t)((lane >> 3) & 1) * 16;

    const __half* Ahi_b = Ahi + (size_t)blockM * K;
    const __half* Bhi_b = Bthi + (size_t)blockN * K;

    // cp.async mapping: thread -> row = tid>>1, two 16B chunks at (tid&1)*2, +1
    auto load_stage = [&](int s) {
        const int k0 = s * BK;
        const uint32_t buf = sb + (s % 3) * STAGE;
        const int row = tid >> 1, ch = (tid & 1) * 2;
        const size_t goff = (size_t)row * K + k0 + ch * 8;
        const uint32_t soff = row * RS + ch * 16;
        cp16(buf + SA_HI + soff,      Ahi_b + goff);
        cp16(buf + SA_HI + soff + 16, Ahi_b + goff + 8);
        cp16(buf + SB_HI + soff,      Bhi_b + goff);
        cp16(buf + SB_HI + soff + 16, Bhi_b + goff + 8);
    };

    float acc[MT][NT][4];
#pragma unroll
    for (int mt = 0; mt < MT; mt++)
#pragma unroll
        for (int nt = 0; nt < NT; nt++)
#pragma unroll
            for (int c = 0; c < 4; c++) acc[mt][nt][c] = 0.f;

    load_stage(0); CP_COMMIT();
    load_stage(1); CP_COMMIT();

    for (int it = 0; it < NITER; ++it) {
        if (it == NITER - 1) { CP_WAIT0(); } else { CP_WAIT1(); }
        __syncthreads();
        if (it + 2 < NITER) { load_stage(it + 2); CP_COMMIT(); }

        const uint32_t buf = sb + (it % 3) * STAGE;

#pragma unroll
        for (int ks = 0; ks < 2; ks++) {
            const uint32_t aHi = buf + SA_HI + aoff + ks * 32;
            const uint32_t bHi = buf + SB_HI + boff + ks * 32;

            uint32_t fAhi[MT][4], fBhi[NT][2];
#pragma unroll
            for (int mt = 0; mt < MT; mt++)
                ldsm4(fAhi[mt], aHi + mt * 16 * RS);
#pragma unroll
            for (int nt = 0; nt < NT; nt += 2)
                ldsm4(&fBhi[nt][0], bHi + nt * 8 * RS);

#pragma unroll
            for (int mt = 0; mt < MT; mt++)
#pragma unroll
                for (int nt = 0; nt < NT; nt++)
                    mma16816(acc[mt][nt], fAhi[mt], fBhi[nt]);
        }
    }

    // output target for OUTMODE 2 (block never straddles NM boundary: 768 % 128 == 0)
    float* Cout = nullptr;
    int cstride = 0, cbase = 0;
    if (OUTMODE == 2) {
        if (blockN < NM) { Cout = Cf0; cstride = NM; cbase = blockN; }
        else             { Cout = Cf1; cstride = NV; cbase = blockN - NM; }
    }

    // epilogue
#pragma unroll
    for (int mt = 0; mt < MT; mt++) {
        const int row0 = blockM + m0 + mt * 16 + g;
#pragma unroll
        for (int nt = 0; nt < NT; nt++) {
            const int coll = n0 + nt * 8 + 2 * t;
            const float bv0 = sBias[coll], bv1 = sBias[coll + 1];
            float v00 = acc[mt][nt][0] + bv0, v01 = acc[mt][nt][1] + bv1;
            float v10 = acc[mt][nt][2] + bv0, v11 = acc[mt][nt][3] + bv1;
            if (SILU) {
                v00 = v00 / (1.f + expf(-v00));
                v01 = v01 / (1.f + expf(-v01));
                v10 = v10 / (1.f + expf(-v10));
                v11 = v11 / (1.f + expf(-v11));
            }
            if (OUTMODE == 2) {
                const int col = cbase + coll;
                float2 a = {v00, v01}, b = {v10, v11};
                *(float2*)(Cout + (size_t)row0 * cstride + col)       = a;
                *(float2*)(Cout + (size_t)(row0 + 8) * cstride + col) = b;
            } else {
                const int col = blockN + coll;
                size_t p0 = (size_t)row0 * HID + col;
                size_t p1 = (size_t)(row0 + 8) * HID + col;
                *(uint32_t*)(Chi + p0) = hpack2(v00, v01);
                *(uint32_t*)(Chi + p1) = hpack2(v10, v11);
            }
        }
    }
}

// ---------------------------------------------------------------------------
// MVN epilogue: 16 threads per (b,h) group, float4 stores.
// ---------------------------------------------------------------------------
__device__ __forceinline__ int triu_idx(int r, int c) {
    return r * (15 - r) / 2 + (c - r - 1);
}

__global__ __launch_bounds__(256)
void mvn_epilogue(const float* __restrict__ lv,
                  float* __restrict__ prec,
                  float* __restrict__ Dout,
                  float* __restrict__ Tout)
{
    constexpr int GP = 16;                 // groups per block (16 threads each)
    __shared__ float s_eta[GP][E_DIM];
    __shared__ float s_d[GP][O_DIM];
    __shared__ float s_dinv[GP][O_DIM];

    const int g = threadIdx.x >> 4;        // 0..15
    const int s = threadIdx.x & 15;        // 0..15
    const size_t bh = (size_t)blockIdx.x * GP + g;

#pragma unroll
    for (int e = s; e < E_DIM; e += 16)
        s_eta[g][e] = lv[bh * E_DIM + e];
    __syncthreads();
    if (s < O_DIM) {
        float d = expf(0.5f * s_eta[g][s]);
        s_d[g][s] = d;
        s_dinv[g][s] = 1.f / d;
    }
    __syncthreads();

    const int i  = s >> 1;                 // row 0..7
    const int kb = (s & 1) * 4;            // col base 0 or 4
    const float* e = s_eta[g];
    const float* dinv = s_dinv[g];

    float pv[4] = {0.f, 0.f, 0.f, 0.f};
    float tv[4], dv[4];
#pragma unroll
    for (int c = 0; c < 4; c++) {
        const int k = kb + c;
        tv[c] = (i == k) ? 1.f : ((i < k) ? e[O_DIM + triu_idx(i, k)] : 0.f);
        dv[c] = (i == k) ? s_d[g][i] : 0.f;
    }
#pragma unroll
    for (int j = 0; j < O_DIM; j++) {
        float tji = (j == i) ? 1.f : ((j < i) ? e[O_DIM + triu_idx(j, i)] : 0.f);
        float w = tji * dinv[j];
#pragma unroll
        for (int c = 0; c < 4; c++) {
            const int k = kb + c;
            float tjk = (j == k) ? 1.f : ((j < k) ? e[O_DIM + triu_idx(j, k)] : 0.f);
            pv[c] = fmaf(w, tjk, pv[c]);
        }
    }

    const size_t base = bh * (O_DIM * O_DIM) + i * O_DIM + kb;
    *(float4*)(prec + base) = *(float4*)pv;
    *(float4*)(Dout + base) = *(float4*)dv;
    *(float4*)(Tout + base) = *(float4*)tv;
}

// ---------------------------------------------------------------------------
// Launch
// ---------------------------------------------------------------------------
extern "C" void kernel_launch(void* const* d_in, const int* in_sizes, int n_in,
                              void* d_out, int out_size)
{
    const float* z  = (const float*)d_in[0];
    const float* W1 = (const float*)d_in[1];
    const float* b1 = (const float*)d_in[2];
    const float* W2 = (const float*)d_in[3];
    const float* b2 = (const float*)d_in[4];
    const float* Wm = (const float*)d_in[5];
    const float* bm = (const float*)d_in[6];
    const float* Wv = (const float*)d_in[7];
    const float* bv = (const float*)d_in[8];

    float* out = (float*)d_out;
    const size_t n_means = (size_t)BATCH * FH * O_DIM;
    const size_t n_mat   = (size_t)BATCH * FH * O_DIM * O_DIM;
    float* means = out;
    float* prec  = out + n_means;
    float* Dout  = prec + n_mat;
    float* Tout  = Dout + n_mat;

    __half *zhi, *ihi, *hhi, *w1hi, *w2hi, *wchi;
    float *lv, *bcat;
    cudaGetSymbolAddress((void**)&zhi, g_zhi);
    cudaGetSymbolAddress((void**)&ihi, g_ihi);
    cudaGetSymbolAddress((void**)&hhi, g_hhi);
    cudaGetSymbolAddress((void**)&w1hi, g_w1hi);
    cudaGetSymbolAddress((void**)&w2hi, g_w2hi);
    cudaGetSymbolAddress((void**)&wchi, g_wchi);
    cudaGetSymbolAddress((void**)&bcat, g_bcat);
    cudaGetSymbolAddress((void**)&lv, g_lv);

    const int SMEM = 3 * 20480 + 512;   // 61952
    cudaFuncSetAttribute((void*)gemm_mma<true, 3>,  cudaFuncAttributeMaxDynamicSharedMemorySize, SMEM);
    cudaFuncSetAttribute((void*)gemm_mma<false, 3>, cudaFuncAttributeMaxDynamicSharedMemorySize, SMEM);
    cudaFuncSetAttribute((void*)gemm_mma<false, 2>, cudaFuncAttributeMaxDynamicSharedMemorySize, SMEM);

    // converts: 3 launches total
    cvt_act<<<(BATCH * HID / 4) / 256, 256>>>(z, zhi);
    convert_w_all<<<dim3(196, HID / 32), 256>>>(W1, W2, Wm, Wv, w1hi, w2hi, wchi);
    concat_bias<<<(NCAT + 255) / 256, 256>>>(bm, bv, bcat);

    // GEMM chain (single-pass fp16, CTA 128x128, BK=32, 2 CTAs/SM)
    gemm_mma<true, 3><<<dim3(HID / 128, BATCH / 128), 256, SMEM>>>(
        zhi, w1hi, b1, nullptr, nullptr, ihi);
    gemm_mma<false, 3><<<dim3(HID / 128, BATCH / 128), 256, SMEM>>>(
        ihi, w2hi, b2, nullptr, nullptr, hhi);
    gemm_mma<false, 2><<<dim3(NCAT / 128, BATCH / 128), 256, SMEM>>>(
        hhi, wchi, bcat, means, lv, nullptr);

    // MVN epilogue (16 groups/block, float4 stores)
    mvn_epilogue<<<(BATCH * FH) / 16, 256>>>(lv, prec, Dout, Tout);
}